// round 1
// baseline (speedup 1.0000x reference)
#include <cuda_runtime.h>

// ---------------- constants (match reference exactly) ----------------
#define T_FRAMES 2049          // 1 + 262144/128
#define NWAV     262144
#define HOPSZ    128
#define MW       16699         // MIN_WIN
#define LEFT     24418         // (65536-16699)//2
#define PADR     32768         // N_FFT/2 reflect pad
#define KPAD     16768         // 131*128  (MW rounded up to 128)
#define NB       96            // n_bins
#define NBIN2    192           // 2 bins (lo,hi) per cqt bin
#define NCOLS    384           // 192 bins x (cos,sin)
#define NC       20            // n_cqcc
#define XW_LEN   282880        // 128*2048 + 16640 + 4096  (exact)
#define ZROWS    2112

// ---------------- device scratch (no allocations allowed) ----------------
__device__ float g_xw[XW_LEN];            // reflect-padded wav, shifted by LEFT
__device__ float g_tab[KPAD * NCOLS];     // hann*cos / hann*sin table (25.8 MB)
__device__ float g_z[ZROWS * NCOLS];      // DFT re/im per frame
__device__ float g_c[T_FRAMES * NC];      // raw cqcc
__device__ float g_cn[T_FRAMES * NC];     // normalized cqcc
__device__ float g_d1[T_FRAMES * NC];     // first delta
__device__ int   g_bins[NBIN2];
__device__ float g_alpha[NB];
__device__ float g_dct[NC * NB];

// ---------------- small constants: bins, alpha, DCT ----------------
__global__ void k_small() {
    int i = threadIdx.x;
    if (i < NB) {
        float cq   = 32.7f * exp2f((float)i / 24.0f);
        float idxf = cq / 8000.0f * 32768.0f;      // cq/(SR/2)*(NUM_FREQ-1)
        int lo = (int)idxf;
        lo = max(0, min(lo, 32767));               // clip to NUM_FREQ-2
        g_bins[2 * i]     = lo;
        g_bins[2 * i + 1] = lo + 1;
        g_alpha[i] = idxf - (float)lo;
    }
    for (int idx = i; idx < NC * NB; idx += blockDim.x) {
        int c = idx / NB, n = idx % NB;
        g_dct[idx] = cospif((float)(c * (2 * n + 1)) / 192.0f);  // cos(pi*c*(2n+1)/(2*96))
    }
}

// ---------------- reflect pad, shifted so frame base = 128*t ----------------
__global__ void k_pad(const float* __restrict__ wav) {
    int i = blockIdx.x * blockDim.x + threadIdx.x;
    if (i >= XW_LEN) return;
    int q = i + (LEFT - PADR);                       // i - 8350
    int idx = (q < 0) ? -q : ((q >= NWAV) ? (2 * NWAV - 2 - q) : q);
    g_xw[i] = wav[idx];
}

// ---------------- basis table: hann[j]*cos/sin(2*pi*bin*j/65536), integer-exact phase ----------------
__global__ void k_tab() {
    int t = blockIdx.x * blockDim.x + threadIdx.x;
    if (t >= KPAD * NBIN2) return;
    int j = t / NBIN2, b = t % NBIN2;
    float2 v = make_float2(0.0f, 0.0f);
    if (j < MW) {
        float h = 0.5f - 0.5f * cospif(2.0f * (float)j / (float)MW);  // periodic hann
        int m = (g_bins[b] * j) & 65535;            // exact phase index
        if (m >= 32768) m -= 65536;                 // center for accuracy
        float s, c;
        sincospif((float)m * (1.0f / 32768.0f), &s, &c);
        v = make_float2(h * c, h * s);              // sign of sin irrelevant (power only)
    }
    ((float2*)g_tab)[j * NBIN2 + b] = v;
}

// ---------------- main GEMM: Z[t, col] = sum_j xw[128t+j] * tab[j, col] ----------------
// block tile: 32 frames x 64 cols, K chunk 128. smem: xs 16KB + ts 32KB = 48KB.
__global__ void __launch_bounds__(256) k_gemm() {
    __shared__ float xs[4096];        // (32-1)*128 + 128 contiguous samples
    __shared__ float ts[128 * 64];
    const int c0  = blockIdx.x * 64;
    const int t0  = blockIdx.y * 32;
    const int tid = threadIdx.x;
    const int tn4 = tid & 15;         // 4-col group
    const int tm2 = tid >> 4;         // 2-frame group
    float acc[2][4] = {};
    const int xbase = t0 * 128;

    for (int j0 = 0; j0 < KPAD; j0 += 128) {
        const float4* xsrc = (const float4*)(g_xw + xbase + j0);
        #pragma unroll
        for (int i = tid; i < 1024; i += 256)
            ((float4*)xs)[i] = xsrc[i];
        #pragma unroll
        for (int i = tid; i < 2048; i += 256) {
            int kk = i >> 4, c4 = i & 15;
            ((float4*)ts)[i] = *(const float4*)(g_tab + (size_t)(j0 + kk) * NCOLS + c0 + c4 * 4);
        }
        __syncthreads();
        #pragma unroll 4
        for (int kk = 0; kk < 128; kk++) {
            float4 b = *(float4*)(ts + kk * 64 + tn4 * 4);
            float a0 = xs[tm2 * 256 + kk];
            float a1 = xs[tm2 * 256 + 128 + kk];
            acc[0][0] = fmaf(a0, b.x, acc[0][0]);
            acc[0][1] = fmaf(a0, b.y, acc[0][1]);
            acc[0][2] = fmaf(a0, b.z, acc[0][2]);
            acc[0][3] = fmaf(a0, b.w, acc[0][3]);
            acc[1][0] = fmaf(a1, b.x, acc[1][0]);
            acc[1][1] = fmaf(a1, b.y, acc[1][1]);
            acc[1][2] = fmaf(a1, b.z, acc[1][2]);
            acc[1][3] = fmaf(a1, b.w, acc[1][3]);
        }
        __syncthreads();
    }
    int t = t0 + tm2 * 2;
    #pragma unroll
    for (int r = 0; r < 2; r++) {
        float4 o = make_float4(acc[r][0], acc[r][1], acc[r][2], acc[r][3]);
        *(float4*)(g_z + (size_t)(t + r) * NCOLS + c0 + tn4 * 4) = o;
    }
}

// ---------------- power -> lerp -> log -> DCT ----------------
__global__ void k_ceps() {
    int t = blockIdx.x;
    __shared__ float sp[NB];
    int f = threadIdx.x;                      // 96 threads
    float4 z = *(const float4*)(g_z + (size_t)t * NCOLS + 4 * f);
    float plo = z.x * z.x + z.y * z.y;
    float phi = z.z * z.z + z.w * z.w;
    float a = g_alpha[f];
    float p = (1.0f - a) * plo + a * phi;
    sp[f] = logf(fmaxf(p, 1e-8f));
    __syncthreads();
    if (f < NC) {
        float s = 0.0f;
        #pragma unroll 8
        for (int n = 0; n < NB; n++) s += sp[n] * g_dct[f * NB + n];
        g_c[t * NC + f] = s;
    }
}

// ---------------- per-coefficient time normalization (ddof=1) ----------------
__global__ void k_norm() {
    int c = blockIdx.x;
    __shared__ float red[256];
    int tid = threadIdx.x;
    float s = 0.0f;
    for (int t = tid; t < T_FRAMES; t += 256) s += g_c[t * NC + c];
    red[tid] = s; __syncthreads();
    for (int o = 128; o; o >>= 1) { if (tid < o) red[tid] += red[tid + o]; __syncthreads(); }
    float mean = red[0] / (float)T_FRAMES;
    __syncthreads();
    float ss = 0.0f;
    for (int t = tid; t < T_FRAMES; t += 256) { float d = g_c[t * NC + c] - mean; ss += d * d; }
    red[tid] = ss; __syncthreads();
    for (int o = 128; o; o >>= 1) { if (tid < o) red[tid] += red[tid + o]; __syncthreads(); }
    float inv = 1.0f / (sqrtf(red[0] / (float)(T_FRAMES - 1)) + 1e-8f);
    for (int t = tid; t < T_FRAMES; t += 256) g_cn[t * NC + c] = (g_c[t * NC + c] - mean) * inv;
}

// ---------------- deltas ----------------
__device__ __forceinline__ float clampf_arr(const float* a, int t, int c) {
    t = min(max(t, 0), T_FRAMES - 1);
    return a[t * NC + c];
}
__global__ void k_d1(float* __restrict__ out) {
    int idx = blockIdx.x * blockDim.x + threadIdx.x;
    if (idx >= T_FRAMES * NC) return;
    int t = idx / NC, c = idx % NC;
    float d = ((clampf_arr(g_cn, t + 1, c) - clampf_arr(g_cn, t - 1, c))
        + 2.0f * (clampf_arr(g_cn, t + 2, c) - clampf_arr(g_cn, t - 2, c))) / 10.0f;
    g_d1[idx] = d;
    out[t * 60 + c]      = g_cn[idx];
    out[t * 60 + 20 + c] = d;
}
__global__ void k_d2(float* __restrict__ out) {
    int idx = blockIdx.x * blockDim.x + threadIdx.x;
    if (idx >= T_FRAMES * NC) return;
    int t = idx / NC, c = idx % NC;
    float d = ((clampf_arr(g_d1, t + 1, c) - clampf_arr(g_d1, t - 1, c))
        + 2.0f * (clampf_arr(g_d1, t + 2, c) - clampf_arr(g_d1, t - 2, c))) / 10.0f;
    out[t * 60 + 40 + c] = d;
}

// ---------------- launch ----------------
extern "C" void kernel_launch(void* const* d_in, const int* in_sizes, int n_in,
                              void* d_out, int out_size) {
    const float* wav = (const float*)d_in[0];
    float* out = (float*)d_out;

    k_small<<<1, 256>>>();
    k_pad<<<(XW_LEN + 255) / 256, 256>>>(wav);
    k_tab<<<(KPAD * NBIN2 + 255) / 256, 256>>>();
    k_gemm<<<dim3(NCOLS / 64, (T_FRAMES + 31) / 32), 256>>>();
    k_ceps<<<T_FRAMES, 96>>>();
    k_norm<<<NC, 256>>>();
    k_d1<<<(T_FRAMES * NC + 255) / 256, 256>>>(out);
    k_d2<<<(T_FRAMES * NC + 255) / 256, 256>>>(out);
}

// round 2
// speedup vs baseline: 1.5502x; 1.5502x over previous
#include <cuda_runtime.h>

// ---------------- constants (match reference exactly) ----------------
#define T_FRAMES 2049          // 1 + 262144/128
#define NWAV     262144
#define MW       16699         // MIN_WIN
#define LEFT     24418         // (65536-16699)//2
#define PADR     32768         // N_FFT/2 reflect pad
#define KPAD     16768         // 131*128
#define KSPLIT   8448          // 66*128  (first K-partition end)
#define NB       96
#define NBIN2    192
#define NCOLS    384           // 192 bins x (cos,sin)
#define NC       20
#define ZROWS    2112          // 33*64
#define XW_LEN   286976        // 2048*128 + KPAD + 8064  (covers last block's window)

// ---------------- device scratch ----------------
__device__ float g_xw[XW_LEN];
__device__ float g_tab[KPAD * NCOLS];          // 25.8 MB
__device__ float g_zp[2 * ZROWS * NCOLS];      // K-split partials
__device__ float g_c[T_FRAMES * NC];
__device__ float g_cn[T_FRAMES * NC];
__device__ float g_d1[T_FRAMES * NC];
__device__ int   g_bins[NBIN2];
__device__ float g_alpha[NB];
__device__ float g_dct[NC * NB];

// ---------------- f32x2 helpers ----------------
__device__ __forceinline__ void fma2(unsigned long long& acc,
                                     unsigned long long a, unsigned long long b) {
    asm("fma.rn.f32x2 %0, %1, %2, %0;" : "+l"(acc) : "l"(a), "l"(b));
}
__device__ __forceinline__ unsigned long long dup2(float x) {
    unsigned long long r;
    asm("mov.b64 %0, {%1, %1};" : "=l"(r) : "f"(x));
    return r;
}

// ---------------- small constants ----------------
__global__ void k_small() {
    int i = threadIdx.x;
    if (i < NB) {
        float cq   = 32.7f * exp2f((float)i / 24.0f);
        float idxf = cq / 8000.0f * 32768.0f;
        int lo = (int)idxf;
        lo = max(0, min(lo, 32767));
        g_bins[2 * i]     = lo;
        g_bins[2 * i + 1] = lo + 1;
        g_alpha[i] = idxf - (float)lo;
    }
    for (int idx = i; idx < NC * NB; idx += blockDim.x) {
        int c = idx / NB, n = idx % NB;
        g_dct[idx] = cospif((float)(c * (2 * n + 1)) / 192.0f);
    }
}

// ---------------- reflect pad, shifted so frame base = 128*t ----------------
__global__ void k_pad(const float* __restrict__ wav) {
    int i = blockIdx.x * blockDim.x + threadIdx.x;
    if (i >= XW_LEN) return;
    int q = i + (LEFT - PADR);
    int idx = (q < 0) ? -q : ((q >= NWAV) ? (2 * NWAV - 2 - q) : q);
    idx = max(0, min(idx, NWAV - 1));
    g_xw[i] = wav[idx];
}

// ---------------- basis table (integer-exact phase) ----------------
__global__ void k_tab() {
    int t = blockIdx.x * blockDim.x + threadIdx.x;
    if (t >= KPAD * NBIN2) return;
    int j = t / NBIN2, b = t % NBIN2;
    float2 v = make_float2(0.0f, 0.0f);
    if (j < MW) {
        float h = 0.5f - 0.5f * cospif(2.0f * (float)j / (float)MW);
        int m = (g_bins[b] * j) & 65535;
        if (m >= 32768) m -= 65536;
        float s, c;
        sincospif((float)m * (1.0f / 32768.0f), &s, &c);
        v = make_float2(h * c, h * s);
    }
    ((float2*)g_tab)[j * NBIN2 + b] = v;
}

// ---------------- main GEMM ----------------
// block tile 64 frames x 64 cols, K chunk 128, K-split 2.
// thread tile 4 frames x 4 cols (2 f32x2 pairs), FFMA2 inner loop.
__global__ void __launch_bounds__(256) k_gemm() {
    extern __shared__ float smem[];
    float* xs = smem;           // 8192 floats: contiguous samples for 64 frames + 128 k
    float* ts = smem + 8192;    // 128 k x 64 cols

    const int c0 = blockIdx.x * 64;
    const int t0 = blockIdx.y * 64;
    const int kb = blockIdx.z;
    const int j_begin = kb ? KSPLIT : 0;
    const int j_end   = kb ? KPAD   : KSPLIT;
    const int tid = threadIdx.x;
    const int cg = tid & 15;    // col group (4 cols = 2 pairs)
    const int fg = tid >> 4;    // frame group (4 frames)
    const int xbase = t0 * 128;

    unsigned long long acc[4][2] = {};

    for (int j0 = j_begin; j0 < j_end; j0 += 128) {
        const float4* xsrc = (const float4*)(g_xw + xbase + j0);
        #pragma unroll
        for (int i = tid; i < 2048; i += 256)
            ((float4*)xs)[i] = xsrc[i];
        #pragma unroll
        for (int i = tid; i < 2048; i += 256) {
            int kk = i >> 4, c4 = i & 15;
            ((float4*)ts)[i] = *(const float4*)(g_tab + (size_t)(j0 + kk) * NCOLS + c0 + c4 * 4);
        }
        __syncthreads();

        #pragma unroll 4
        for (int kk0 = 0; kk0 < 128; kk0 += 4) {
            float4 af[4];
            #pragma unroll
            for (int r = 0; r < 4; r++)
                af[r] = *(const float4*)(xs + (fg * 4 + r) * 128 + kk0);
            #pragma unroll
            for (int k = 0; k < 4; k++) {
                ulonglong2 bb = *(const ulonglong2*)(ts + (kk0 + k) * 64 + cg * 4);
                #pragma unroll
                for (int r = 0; r < 4; r++) {
                    unsigned long long ad = dup2(((const float*)&af[r])[k]);
                    fma2(acc[r][0], ad, bb.x);
                    fma2(acc[r][1], ad, bb.y);
                }
            }
        }
        __syncthreads();
    }

    float* zout = g_zp + (size_t)kb * (ZROWS * NCOLS);
    #pragma unroll
    for (int r = 0; r < 4; r++) {
        int t = t0 + fg * 4 + r;
        ulonglong2 v;
        v.x = acc[r][0];
        v.y = acc[r][1];
        *(ulonglong2*)(zout + (size_t)t * NCOLS + c0 + cg * 4) = v;
    }
}

// ---------------- power -> lerp -> log -> DCT ----------------
__global__ void k_ceps() {
    int t = blockIdx.x;
    __shared__ float sp[NB];
    int f = threadIdx.x;  // 96 threads
    float4 z0 = *(const float4*)(g_zp + (size_t)t * NCOLS + 4 * f);
    float4 z1 = *(const float4*)(g_zp + (size_t)(ZROWS * NCOLS) + (size_t)t * NCOLS + 4 * f);
    float re0 = z0.x + z1.x, im0 = z0.y + z1.y;
    float re1 = z0.z + z1.z, im1 = z0.w + z1.w;
    float plo = re0 * re0 + im0 * im0;
    float phi = re1 * re1 + im1 * im1;
    float a = g_alpha[f];
    float p = (1.0f - a) * plo + a * phi;
    sp[f] = logf(fmaxf(p, 1e-8f));
    __syncthreads();
    if (f < NC) {
        float s = 0.0f;
        #pragma unroll 8
        for (int n = 0; n < NB; n++) s += sp[n] * g_dct[f * NB + n];
        g_c[t * NC + f] = s;
    }
}

// ---------------- per-coefficient time normalization (ddof=1) ----------------
__global__ void k_norm() {
    int c = blockIdx.x;
    __shared__ float red[256];
    int tid = threadIdx.x;
    float s = 0.0f;
    for (int t = tid; t < T_FRAMES; t += 256) s += g_c[t * NC + c];
    red[tid] = s; __syncthreads();
    for (int o = 128; o; o >>= 1) { if (tid < o) red[tid] += red[tid + o]; __syncthreads(); }
    float mean = red[0] / (float)T_FRAMES;
    __syncthreads();
    float ss = 0.0f;
    for (int t = tid; t < T_FRAMES; t += 256) { float d = g_c[t * NC + c] - mean; ss += d * d; }
    red[tid] = ss; __syncthreads();
    for (int o = 128; o; o >>= 1) { if (tid < o) red[tid] += red[tid + o]; __syncthreads(); }
    float inv = 1.0f / (sqrtf(red[0] / (float)(T_FRAMES - 1)) + 1e-8f);
    for (int t = tid; t < T_FRAMES; t += 256) g_cn[t * NC + c] = (g_c[t * NC + c] - mean) * inv;
}

// ---------------- deltas ----------------
__device__ __forceinline__ float clampf_arr(const float* a, int t, int c) {
    t = min(max(t, 0), T_FRAMES - 1);
    return a[t * NC + c];
}
__global__ void k_d1(float* __restrict__ out) {
    int idx = blockIdx.x * blockDim.x + threadIdx.x;
    if (idx >= T_FRAMES * NC) return;
    int t = idx / NC, c = idx % NC;
    float d = ((clampf_arr(g_cn, t + 1, c) - clampf_arr(g_cn, t - 1, c))
        + 2.0f * (clampf_arr(g_cn, t + 2, c) - clampf_arr(g_cn, t - 2, c))) / 10.0f;
    g_d1[idx] = d;
    out[t * 60 + c]      = g_cn[idx];
    out[t * 60 + 20 + c] = d;
}
__global__ void k_d2(float* __restrict__ out) {
    int idx = blockIdx.x * blockDim.x + threadIdx.x;
    if (idx >= T_FRAMES * NC) return;
    int t = idx / NC, c = idx % NC;
    float d = ((clampf_arr(g_d1, t + 1, c) - clampf_arr(g_d1, t - 1, c))
        + 2.0f * (clampf_arr(g_d1, t + 2, c) - clampf_arr(g_d1, t - 2, c))) / 10.0f;
    out[t * 60 + 40 + c] = d;
}

// ---------------- launch ----------------
extern "C" void kernel_launch(void* const* d_in, const int* in_sizes, int n_in,
                              void* d_out, int out_size) {
    const float* wav = (const float*)d_in[0];
    float* out = (float*)d_out;

    cudaFuncSetAttribute(k_gemm, cudaFuncAttributeMaxDynamicSharedMemorySize, 65536);

    k_small<<<1, 256>>>();
    k_pad<<<(XW_LEN + 255) / 256, 256>>>(wav);
    k_tab<<<(KPAD * NBIN2 + 255) / 256, 256>>>();
    k_gemm<<<dim3(NCOLS / 64, ZROWS / 64, 2), 256, 65536>>>();
    k_ceps<<<T_FRAMES, 96>>>();
    k_norm<<<NC, 256>>>();
    k_d1<<<(T_FRAMES * NC + 255) / 256, 256>>>(out);
    k_d2<<<(T_FRAMES * NC + 255) / 256, 256>>>(out);
}

// round 3
// speedup vs baseline: 1.8772x; 1.2109x over previous
#include <cuda_runtime.h>

// ---------------- constants ----------------
#define T_FRAMES 2049
#define NWAV     262144
#define MW       16699
#define LEFT     24418
#define PADR     32768
#define KPAD     16768          // 131*128
#define NCHUNK   131
#define NSPLIT   16
#define NB       96
#define NBIN2    192
#define NCOLS    384
#define NC       20
#define ZROWS    2176           // 17*128
#define XW_LEN   295168         // 2048*128 + 16640 + 16384

// ---------------- device scratch ----------------
__device__ float g_xw[XW_LEN];
__device__ float g_tab[KPAD * NCOLS];               // 25.8 MB
__device__ float g_zp[NSPLIT * ZROWS * NCOLS];      // 53.5 MB K-split partials
__device__ float g_c[T_FRAMES * NC];
__device__ float g_cn[T_FRAMES * NC];
__device__ float g_d1[T_FRAMES * NC];
__device__ int   g_bins[NBIN2];
__device__ float g_alpha[NB];
__device__ float g_dct[NC * NB];

// ---------------- f32x2 helpers ----------------
__device__ __forceinline__ void fma2(unsigned long long& acc,
                                     unsigned long long a, unsigned long long b) {
    asm("fma.rn.f32x2 %0, %1, %2, %0;" : "+l"(acc) : "l"(a), "l"(b));
}
__device__ __forceinline__ unsigned long long dup2(float x) {
    unsigned long long r;
    asm("mov.b64 %0, {%1, %1};" : "=l"(r) : "f"(x));
    return r;
}

// ---------------- small constants ----------------
__global__ void k_small() {
    int i = threadIdx.x;
    if (i < NB) {
        float cq   = 32.7f * exp2f((float)i / 24.0f);
        float idxf = cq / 8000.0f * 32768.0f;
        int lo = (int)idxf;
        lo = max(0, min(lo, 32767));
        g_bins[2 * i]     = lo;
        g_bins[2 * i + 1] = lo + 1;
        g_alpha[i] = idxf - (float)lo;
    }
    for (int idx = i; idx < NC * NB; idx += blockDim.x) {
        int c = idx / NB, n = idx % NB;
        g_dct[idx] = cospif((float)(c * (2 * n + 1)) / 192.0f);
    }
}

// ---------------- reflect pad (shifted so frame base = 128*t) ----------------
__global__ void k_pad(const float* __restrict__ wav) {
    int i = blockIdx.x * blockDim.x + threadIdx.x;
    if (i >= XW_LEN) return;
    int q = i + (LEFT - PADR);
    int idx = (q < 0) ? -q : ((q >= NWAV) ? (2 * NWAV - 2 - q) : q);
    idx = max(0, min(idx, NWAV - 1));
    g_xw[i] = wav[idx];
}

// ---------------- basis table (integer-exact phase) ----------------
__global__ void k_tab() {
    int t = blockIdx.x * blockDim.x + threadIdx.x;
    if (t >= KPAD * NBIN2) return;
    int j = t / NBIN2, b = t % NBIN2;
    float2 v = make_float2(0.0f, 0.0f);
    if (j < MW) {
        float h = 0.5f - 0.5f * cospif(2.0f * (float)j / (float)MW);
        int m = (g_bins[b] * j) & 65535;
        if (m >= 32768) m -= 65536;
        float s, c;
        sincospif((float)m * (1.0f / 32768.0f), &s, &c);
        v = make_float2(h * c, h * s);
    }
    ((float2*)g_tab)[j * NBIN2 + b] = v;
}

// ---------------- main GEMM ----------------
// block tile 128 frames x 128 cols, K chunk 128, K split in 16.
// thread tile 8f x 8c (cols split in two 64-halves for conflict-free LDS.128).
__global__ void __launch_bounds__(256) k_gemm() {
    extern __shared__ float smem[];
    float* xs = smem;            // 16384 floats: 127*128 + 128 samples
    float* ts = smem + 16384;    // 128 k x 128 cols

    const int c0 = blockIdx.x * 128;
    const int t0 = blockIdx.y * 128;
    const int sp = blockIdx.z;
    const int ch0 = (sp * NCHUNK) / NSPLIT;
    const int ch1 = ((sp + 1) * NCHUNK) / NSPLIT;
    const int tid = threadIdx.x;
    const int cg = tid & 15;
    const int fg = tid >> 4;
    const int xbase = t0 * 128;

    unsigned long long acc[8][4] = {};

    for (int ch = ch0; ch < ch1; ch++) {
        const int j0 = ch * 128;
        const float4* xsrc = (const float4*)(g_xw + xbase + j0);
        #pragma unroll
        for (int i = tid; i < 4096; i += 256)
            ((float4*)xs)[i] = xsrc[i];
        #pragma unroll
        for (int i = tid; i < 4096; i += 256) {
            int kk = i >> 5, c4 = i & 31;
            ((float4*)ts)[i] = *(const float4*)(g_tab + (size_t)(j0 + kk) * NCOLS + c0 + c4 * 4);
        }
        __syncthreads();

        for (int kk0 = 0; kk0 < 128; kk0 += 4) {
            float4 af[8];
            #pragma unroll
            for (int r = 0; r < 8; r++)
                af[r] = *(const float4*)(xs + (fg * 8 + r) * 128 + kk0);
            #pragma unroll
            for (int k = 0; k < 4; k++) {
                ulonglong2 b0 = *(const ulonglong2*)(ts + (kk0 + k) * 128 + cg * 4);
                ulonglong2 b1 = *(const ulonglong2*)(ts + (kk0 + k) * 128 + 64 + cg * 4);
                #pragma unroll
                for (int r = 0; r < 8; r++) {
                    unsigned long long ad = dup2(((const float*)&af[r])[k]);
                    fma2(acc[r][0], ad, b0.x);
                    fma2(acc[r][1], ad, b0.y);
                    fma2(acc[r][2], ad, b1.x);
                    fma2(acc[r][3], ad, b1.y);
                }
            }
        }
        __syncthreads();
    }

    float* zout = g_zp + (size_t)sp * (ZROWS * NCOLS);
    #pragma unroll
    for (int r = 0; r < 8; r++) {
        int t = t0 + fg * 8 + r;
        ulonglong2 v0, v1;
        v0.x = acc[r][0]; v0.y = acc[r][1];
        v1.x = acc[r][2]; v1.y = acc[r][3];
        *(ulonglong2*)(zout + (size_t)t * NCOLS + c0 + cg * 4)      = v0;
        *(ulonglong2*)(zout + (size_t)t * NCOLS + c0 + 64 + cg * 4) = v1;
    }
}

// ---------------- reduce splits -> power -> lerp -> log -> DCT ----------------
__global__ void k_ceps() {
    int t = blockIdx.x;
    __shared__ float sp[NB];
    int f = threadIdx.x;  // 96 threads
    float4 z = make_float4(0.f, 0.f, 0.f, 0.f);
    #pragma unroll
    for (int s = 0; s < NSPLIT; s++) {
        float4 v = *(const float4*)(g_zp + ((size_t)s * ZROWS + t) * NCOLS + 4 * f);
        z.x += v.x; z.y += v.y; z.z += v.z; z.w += v.w;
    }
    float plo = z.x * z.x + z.y * z.y;
    float phi = z.z * z.z + z.w * z.w;
    float a = g_alpha[f];
    float p = (1.0f - a) * plo + a * phi;
    sp[f] = logf(fmaxf(p, 1e-8f));
    __syncthreads();
    if (f < NC) {
        float s = 0.0f;
        #pragma unroll 8
        for (int n = 0; n < NB; n++) s += sp[n] * g_dct[f * NB + n];
        g_c[t * NC + f] = s;
    }
}

// ---------------- per-coefficient time normalization (ddof=1) ----------------
__global__ void k_norm() {
    int c = blockIdx.x;
    __shared__ float red[256];
    int tid = threadIdx.x;
    float s = 0.0f;
    for (int t = tid; t < T_FRAMES; t += 256) s += g_c[t * NC + c];
    red[tid] = s; __syncthreads();
    for (int o = 128; o; o >>= 1) { if (tid < o) red[tid] += red[tid + o]; __syncthreads(); }
    float mean = red[0] / (float)T_FRAMES;
    __syncthreads();
    float ss = 0.0f;
    for (int t = tid; t < T_FRAMES; t += 256) { float d = g_c[t * NC + c] - mean; ss += d * d; }
    red[tid] = ss; __syncthreads();
    for (int o = 128; o; o >>= 1) { if (tid < o) red[tid] += red[tid + o]; __syncthreads(); }
    float inv = 1.0f / (sqrtf(red[0] / (float)(T_FRAMES - 1)) + 1e-8f);
    for (int t = tid; t < T_FRAMES; t += 256) g_cn[t * NC + c] = (g_c[t * NC + c] - mean) * inv;
}

// ---------------- deltas ----------------
__device__ __forceinline__ float clampf_arr(const float* a, int t, int c) {
    t = min(max(t, 0), T_FRAMES - 1);
    return a[t * NC + c];
}
__global__ void k_d1(float* __restrict__ out) {
    int idx = blockIdx.x * blockDim.x + threadIdx.x;
    if (idx >= T_FRAMES * NC) return;
    int t = idx / NC, c = idx % NC;
    float d = ((clampf_arr(g_cn, t + 1, c) - clampf_arr(g_cn, t - 1, c))
        + 2.0f * (clampf_arr(g_cn, t + 2, c) - clampf_arr(g_cn, t - 2, c))) / 10.0f;
    g_d1[idx] = d;
    out[t * 60 + c]      = g_cn[idx];
    out[t * 60 + 20 + c] = d;
}
__global__ void k_d2(float* __restrict__ out) {
    int idx = blockIdx.x * blockDim.x + threadIdx.x;
    if (idx >= T_FRAMES * NC) return;
    int t = idx / NC, c = idx % NC;
    float d = ((clampf_arr(g_d1, t + 1, c) - clampf_arr(g_d1, t - 1, c))
        + 2.0f * (clampf_arr(g_d1, t + 2, c) - clampf_arr(g_d1, t - 2, c))) / 10.0f;
    out[t * 60 + 40 + c] = d;
}

// ---------------- launch ----------------
extern "C" void kernel_launch(void* const* d_in, const int* in_sizes, int n_in,
                              void* d_out, int out_size) {
    const float* wav = (const float*)d_in[0];
    float* out = (float*)d_out;

    cudaFuncSetAttribute(k_gemm, cudaFuncAttributeMaxDynamicSharedMemorySize, 131072);

    k_small<<<1, 256>>>();
    k_pad<<<(XW_LEN + 255) / 256, 256>>>(wav);
    k_tab<<<(KPAD * NBIN2 + 255) / 256, 256>>>();
    k_gemm<<<dim3(NCOLS / 128, ZROWS / 128, NSPLIT), 256, 131072>>>();
    k_ceps<<<T_FRAMES, 96>>>();
    k_norm<<<NC, 256>>>();
    k_d1<<<(T_FRAMES * NC + 255) / 256, 256>>>(out);
    k_d2<<<(T_FRAMES * NC + 255) / 256, 256>>>(out);
}

// round 5
// speedup vs baseline: 9.5953x; 5.1115x over previous
#include <cuda_runtime.h>
#include <cstdint>

// ---------------- constants ----------------
#define T_FRAMES 2049
#define NWAV     262144
#define MW       16699
#define LEFT     24418
#define PADR     32768
#define NB       96
#define NBIN2    192
#define NC       20
#define NF       576            // 192 bins x 3 sub-frequencies (center, -d, +d)
#define ECOLS    2304           // [full 1152 | partial 1152] float cols
#define SROWS    2240           // stage-1 rows (35*64), covers s <= 2178
#define GROWS    2368           // allocated G rows (covers t+130 <= 2305)
#define XW_LEN   286720         // 128*2240
#define TTILE    128
#define TT       17             // ceil(2049/128) -> t padded to 2176
#define ZROWST   2176
#define FTILE    16             // complex freqs per stage-2 block
#define FT       36

// ---------------- device scratch ----------------
__device__ float g_xw[XW_LEN];
__device__ float g_e[128 * ECOLS];          // stage-1 basis   1.18 MB
__device__ float g_w[131 * 1152];           // stage-2 taps (coeff folded)
__device__ float g_g[(size_t)GROWS * ECOLS];// stage-1 out     21.8 MB
__device__ float g_z[(size_t)ZROWST * 1152];// stage-2 out     10 MB
__device__ float g_c[T_FRAMES * NC];
__device__ float g_cn[T_FRAMES * NC];
__device__ float g_d1[T_FRAMES * NC];
__device__ int   g_bins[NBIN2];
__device__ float g_alpha[NB];
__device__ float g_dct[NC * NB];

// ---------------- f32x2 helpers ----------------
__device__ __forceinline__ void fma2(unsigned long long& acc,
                                     unsigned long long a, unsigned long long b) {
    asm("fma.rn.f32x2 %0, %1, %2, %0;" : "+l"(acc) : "l"(a), "l"(b));
}
__device__ __forceinline__ unsigned long long dup2(float x) {
    unsigned long long r;
    asm("mov.b64 %0, {%1, %1};" : "=l"(r) : "f"(x));
    return r;
}

// ---------------- small constants ----------------
__global__ void k_small() {
    int i = threadIdx.x;
    if (i < NB) {
        float cq   = 32.7f * exp2f((float)i / 24.0f);
        float idxf = cq / 8000.0f * 32768.0f;
        int lo = (int)idxf;
        lo = max(0, min(lo, 32767));
        g_bins[2 * i]     = lo;
        g_bins[2 * i + 1] = lo + 1;
        g_alpha[i] = idxf - (float)lo;
    }
    for (int idx = i; idx < NC * NB; idx += blockDim.x) {
        int c = idx / NB, n = idx % NB;
        g_dct[idx] = cospif((float)(c * (2 * n + 1)) / 192.0f);
    }
}

// ---------------- reflect pad (frame base = 128*t) ----------------
__global__ void k_pad(const float* __restrict__ wav) {
    int i = blockIdx.x * blockDim.x + threadIdx.x;
    if (i >= XW_LEN) return;
    int q = i + (LEFT - PADR);
    int idx = (q < 0) ? -q : ((q >= NWAV) ? (2 * NWAV - 2 - q) : q);
    idx = max(0, min(idx, NWAV - 1));
    g_xw[i] = wav[idx];
}

// ---------------- stage-1 basis: e^{-i theta_f r}, full (r<128) + partial (r<59) ----------------
__global__ void k_e() {
    int fi = blockIdx.x;          // 0..575
    int r  = threadIdx.x;         // 0..127
    int bi = fi / 3, j = fi % 3;
    int b  = g_bins[bi];
    double theta = 6.283185307179586476925286766559 *
                   ((double)b / 65536.0 + ((j == 1) ? -1.0 : (j == 2) ? 1.0 : 0.0) / (double)MW);
    double s, c;
    sincos(theta * (double)r, &s, &c);
    float re = (float)c, im = (float)(-s);
    g_e[r * ECOLS + 2 * fi]     = re;
    g_e[r * ECOLS + 2 * fi + 1] = im;
    float rp = (r < 59) ? re : 0.0f;
    float ip = (r < 59) ? im : 0.0f;
    g_e[r * ECOLS + 1152 + 2 * fi]     = rp;
    g_e[r * ECOLS + 1152 + 2 * fi + 1] = ip;
}

// ---------------- stage-2 taps: coeff * e^{-i theta_f * 128u}, exact rational phase ----------------
__global__ void k_w() {
    int fi = blockIdx.x;          // 0..575
    int u  = threadIdx.x;         // 0..130 (block of 160)
    if (u >= 131) return;
    int bi = fi / 3, j = fi % 3;
    int b  = g_bins[bi];
    double coeff = (j == 0) ? 0.5 : -0.25;
    long long bu = (long long)b * (long long)u;
    double fracA = (double)(bu & 511) / 512.0;              // (b*128u/65536) mod 1
    int m2 = (128 * u) % MW;
    double fracB = (double)m2 / (double)MW;                 // (128u/MW) mod 1
    double fr = fracA + ((j == 1) ? -fracB : (j == 2) ? fracB : 0.0);
    double s, c;
    sincospi(2.0 * fr, &s, &c);
    g_w[u * 1152 + 2 * fi]     = (float)(coeff * c);
    g_w[u * 1152 + 2 * fi + 1] = (float)(-coeff * s);
}

// ---------------- stage 1: G[s, col] = sum_{r<128} xw[128s + r] * E[r, col] ----------------
// block 64 rows x 64 cols, K = 128 (single chunk), thread tile 4x4, FFMA2.
__global__ void __launch_bounds__(256) k_s1() {
    extern __shared__ float smem[];
    float* xs = smem;            // 8192 floats
    float* ts = smem + 8192;     // 128 x 64

    const int c0 = blockIdx.x * 64;
    const int s0 = blockIdx.y * 64;
    const int tid = threadIdx.x;
    const int cg = tid & 15;
    const int fg = tid >> 4;

    const float4* xsrc = (const float4*)(g_xw + s0 * 128);
    #pragma unroll
    for (int i = tid; i < 2048; i += 256)
        ((float4*)xs)[i] = xsrc[i];
    #pragma unroll
    for (int i = tid; i < 2048; i += 256) {
        int kk = i >> 4, c4 = i & 15;
        ((float4*)ts)[i] = *(const float4*)(g_e + kk * ECOLS + c0 + c4 * 4);
    }
    __syncthreads();

    unsigned long long acc[4][2] = {};
    #pragma unroll 4
    for (int kk0 = 0; kk0 < 128; kk0 += 4) {
        float4 af[4];
        #pragma unroll
        for (int r = 0; r < 4; r++)
            af[r] = *(const float4*)(xs + (fg * 4 + r) * 128 + kk0);
        #pragma unroll
        for (int k = 0; k < 4; k++) {
            ulonglong2 bb = *(const ulonglong2*)(ts + (kk0 + k) * 64 + cg * 4);
            #pragma unroll
            for (int r = 0; r < 4; r++) {
                unsigned long long ad = dup2(((const float*)&af[r])[k]);
                fma2(acc[r][0], ad, bb.x);
                fma2(acc[r][1], ad, bb.y);
            }
        }
    }

    #pragma unroll
    for (int r = 0; r < 4; r++) {
        int s = s0 + fg * 4 + r;
        ulonglong2 v;
        v.x = acc[r][0]; v.y = acc[r][1];
        *(ulonglong2*)(g_g + (size_t)s * ECOLS + c0 + cg * 4) = v;
    }
}

// ---------------- stage 2: Z[t,f] = sum_{u<130} W[u,f]*G[t+u,f] + W[130,f]*Gp[t+130,f] ----------------
// block: 128 t x 16 complex freqs. threads 256 = 16 f x 16 tgroups (8 t each).
#define GS_STRIDE 259
__global__ void __launch_bounds__(256) k_s2() {
    extern __shared__ float smem[];
    float2* Gs = (float2*)smem;                       // [16][259]
    float2* Gp = Gs + 16 * GS_STRIDE;                 // [16][129]
    float2* Ws = Gp + 16 * 129;                       // [131][16]

    const int fc0 = blockIdx.x * FTILE;               // complex-freq base
    const int t0  = blockIdx.y * TTILE;
    const int tid = threadIdx.x;

    // load full G tile: rows t0..t0+257, transpose to [f][row]
    for (int idx = tid; idx < 258 * 8; idx += 256) {
        int row = idx >> 3, p = idx & 7;
        float4 v = *(const float4*)(g_g + (size_t)(t0 + row) * ECOLS + fc0 * 2 + p * 4);
        Gs[(2 * p) * GS_STRIDE + row]     = make_float2(v.x, v.y);
        Gs[(2 * p + 1) * GS_STRIDE + row] = make_float2(v.z, v.w);
    }
    // partial G tile: rows t0+130..t0+257
    for (int idx = tid; idx < 128 * 8; idx += 256) {
        int row = idx >> 3, p = idx & 7;
        float4 v = *(const float4*)(g_g + (size_t)(t0 + 130 + row) * ECOLS + 1152 + fc0 * 2 + p * 4);
        Gp[(2 * p) * 129 + row]     = make_float2(v.x, v.y);
        Gp[(2 * p + 1) * 129 + row] = make_float2(v.z, v.w);
    }
    // taps
    for (int idx = tid; idx < 131 * 8; idx += 256) {
        int u = idx >> 3, p = idx & 7;
        float4 v = *(const float4*)(g_w + u * 1152 + fc0 * 2 + p * 4);
        Ws[u * 16 + 2 * p]     = make_float2(v.x, v.y);
        Ws[u * 16 + 2 * p + 1] = make_float2(v.z, v.w);
    }
    __syncthreads();

    const int f  = tid & 15;
    const int tg = tid >> 4;
    const float2* gcol = Gs + f * GS_STRIDE + tg * 8;
    float2 acc[8];
    #pragma unroll
    for (int r = 0; r < 8; r++) acc[r] = make_float2(0.f, 0.f);

    #pragma unroll 2
    for (int u = 0; u < 130; u++) {
        float2 w = Ws[u * 16 + f];
        #pragma unroll
        for (int r = 0; r < 8; r++) {
            float2 g = gcol[u + r];
            acc[r].x = fmaf(w.x, g.x, acc[r].x);
            acc[r].x = fmaf(-w.y, g.y, acc[r].x);
            acc[r].y = fmaf(w.x, g.y, acc[r].y);
            acc[r].y = fmaf(w.y, g.x, acc[r].y);
        }
    }
    {
        float2 w = Ws[130 * 16 + f];
        const float2* gp = Gp + f * 129 + tg * 8;
        #pragma unroll
        for (int r = 0; r < 8; r++) {
            float2 g = gp[r];
            acc[r].x = fmaf(w.x, g.x, acc[r].x);
            acc[r].x = fmaf(-w.y, g.y, acc[r].x);
            acc[r].y = fmaf(w.x, g.y, acc[r].y);
            acc[r].y = fmaf(w.y, g.x, acc[r].y);
        }
    }

    #pragma unroll
    for (int r = 0; r < 8; r++) {
        int t = t0 + tg * 8 + r;
        *(float2*)(g_z + (size_t)t * 1152 + (fc0 + f) * 2) = acc[r];
    }
}

// ---------------- combine triples -> power -> lerp -> log -> DCT ----------------
__global__ void k_ceps() {
    int t = blockIdx.x;
    __shared__ float sp[NB];
    int f = threadIdx.x;  // 96 threads
    const float* zr = g_z + (size_t)t * 1152 + 12 * f;
    float4 a = *(const float4*)(zr);
    float4 b = *(const float4*)(zr + 4);
    float4 c = *(const float4*)(zr + 8);
    float lre = a.x + a.z + b.x, lim = a.y + a.w + b.y;
    float hre = b.z + c.x + c.z, him = b.w + c.y + c.w;
    float plo = lre * lre + lim * lim;
    float phi = hre * hre + him * him;
    float al = g_alpha[f];
    float p = (1.0f - al) * plo + al * phi;
    sp[f] = logf(fmaxf(p, 1e-8f));
    __syncthreads();
    if (f < NC) {
        float s = 0.0f;
        #pragma unroll 8
        for (int n = 0; n < NB; n++) s += sp[n] * g_dct[f * NB + n];
        g_c[t * NC + f] = s;
    }
}

// ---------------- per-coefficient time normalization (ddof=1) ----------------
__global__ void k_norm() {
    int c = blockIdx.x;
    __shared__ float red[256];
    int tid = threadIdx.x;
    float s = 0.0f;
    for (int t = tid; t < T_FRAMES; t += 256) s += g_c[t * NC + c];
    red[tid] = s; __syncthreads();
    for (int o = 128; o; o >>= 1) { if (tid < o) red[tid] += red[tid + o]; __syncthreads(); }
    float mean = red[0] / (float)T_FRAMES;
    __syncthreads();
    float ss = 0.0f;
    for (int t = tid; t < T_FRAMES; t += 256) { float d = g_c[t * NC + c] - mean; ss += d * d; }
    red[tid] = ss; __syncthreads();
    for (int o = 128; o; o >>= 1) { if (tid < o) red[tid] += red[tid + o]; __syncthreads(); }
    float inv = 1.0f / (sqrtf(red[0] / (float)(T_FRAMES - 1)) + 1e-8f);
    for (int t = tid; t < T_FRAMES; t += 256) g_cn[t * NC + c] = (g_c[t * NC + c] - mean) * inv;
}

// ---------------- deltas ----------------
__device__ __forceinline__ float clampf_arr(const float* a, int t, int c) {
    t = min(max(t, 0), T_FRAMES - 1);
    return a[t * NC + c];
}
__global__ void k_d1(float* __restrict__ out) {
    int idx = blockIdx.x * blockDim.x + threadIdx.x;
    if (idx >= T_FRAMES * NC) return;
    int t = idx / NC, c = idx % NC;
    float d = ((clampf_arr(g_cn, t + 1, c) - clampf_arr(g_cn, t - 1, c))
        + 2.0f * (clampf_arr(g_cn, t + 2, c) - clampf_arr(g_cn, t - 2, c))) / 10.0f;
    g_d1[idx] = d;
    out[t * 60 + c]      = g_cn[idx];
    out[t * 60 + 20 + c] = d;
}
__global__ void k_d2(float* __restrict__ out) {
    int idx = blockIdx.x * blockDim.x + threadIdx.x;
    if (idx >= T_FRAMES * NC) return;
    int t = idx / NC, c = idx % NC;
    float d = ((clampf_arr(g_d1, t + 1, c) - clampf_arr(g_d1, t - 1, c))
        + 2.0f * (clampf_arr(g_d1, t + 2, c) - clampf_arr(g_d1, t - 2, c))) / 10.0f;
    out[t * 60 + 40 + c] = d;
}

// ---------------- launch ----------------
extern "C" void kernel_launch(void* const* d_in, const int* in_sizes, int n_in,
                              void* d_out, int out_size) {
    const float* wav = (const float*)d_in[0];
    float* out = (float*)d_out;

    const int s1_smem = 65536;
    const int s2_smem = (16 * GS_STRIDE + 16 * 129 + 131 * 16) * 8;  // 66432
    cudaFuncSetAttribute(k_s1, cudaFuncAttributeMaxDynamicSharedMemorySize, s1_smem);
    cudaFuncSetAttribute(k_s2, cudaFuncAttributeMaxDynamicSharedMemorySize, s2_smem);

    k_small<<<1, 256>>>();
    k_pad<<<(XW_LEN + 255) / 256, 256>>>(wav);
    k_e<<<NF, 128>>>();
    k_w<<<NF, 160>>>();
    k_s1<<<dim3(ECOLS / 64, SROWS / 64), 256, s1_smem>>>();
    k_s2<<<dim3(FT, TT), 256, s2_smem>>>();
    k_ceps<<<T_FRAMES, 96>>>();
    k_norm<<<NC, 256>>>();
    k_d1<<<(T_FRAMES * NC + 255) / 256, 256>>>(out);
    k_d2<<<(T_FRAMES * NC + 255) / 256, 256>>>(out);
}

// round 6
// speedup vs baseline: 11.0211x; 1.1486x over previous
#include <cuda_runtime.h>
#include <cstdint>

// ---------------- constants ----------------
#define T_FRAMES 2049
#define NWAV     262144
#define MW       16699
#define LEFT     24418
#define PADR     32768
#define NB       96
#define NC       20
#define NF       576            // 192 bins x 3 sub-frequencies
#define ECOLS    2304           // [full 1152 | partial 1152]
#define SROWS    2240
#define GROWS    2368
#define XW_LEN   286720         // 128*2240
#define TTILE    128
#define TT       17
#define ZROWST   2176
#define FTILE    16
#define FT       36
#define WROWS    137            // 0..129 full taps, 130..135 zero, 136 partial tap

// setup kernel block ranges
#define PAD_BLKS 1120           // 286720/256
#define E_BLKS   288            // 2 fi per block
#define W_ELEMS  (NF * WROWS)   // 78912
#define W_BLKS   309
#define SETUP_BLKS (PAD_BLKS + E_BLKS + W_BLKS + 1)

// ---------------- device scratch ----------------
__device__ float g_xw[XW_LEN];
__device__ float g_e[128 * ECOLS];
__device__ float g_w[WROWS * 1152];
__device__ float g_g[(size_t)GROWS * ECOLS];
__device__ float g_z[(size_t)ZROWST * 1152];
__device__ float g_c[T_FRAMES * NC];
__device__ float g_alpha[NB];
__device__ float g_dct[NC * NB];

// ---------------- f32x2 helpers ----------------
__device__ __forceinline__ void fma2(unsigned long long& acc,
                                     unsigned long long a, unsigned long long b) {
    asm("fma.rn.f32x2 %0, %1, %2, %0;" : "+l"(acc) : "l"(a), "l"(b));
}
__device__ __forceinline__ unsigned long long dup2(float x) {
    unsigned long long r;
    asm("mov.b64 %0, {%1, %1};" : "=l"(r) : "f"(x));
    return r;
}
__device__ __forceinline__ unsigned long long pk2(float x, float y) {
    unsigned long long r;
    asm("mov.b64 %0, {%1, %2};" : "=l"(r) : "f"(x), "f"(y));
    return r;
}
__device__ __forceinline__ float2 upk2(unsigned long long v) {
    float2 r;
    asm("mov.b64 {%0, %1}, %2;" : "=f"(r.x), "=f"(r.y) : "l"(v));
    return r;
}

// ---------------- inline bin computation (must match alpha path) ----------------
__device__ __forceinline__ int bin_of(int bi) {   // bi 0..191
    int i = bi >> 1;
    float cq   = 32.7f * exp2f((float)i / 24.0f);
    float idxf = cq / 8000.0f * 32768.0f;
    int lo = (int)idxf;
    lo = max(0, min(lo, 32767));
    return lo + (bi & 1);
}

// ---------------- fused setup: pad | stage-1 basis | stage-2 taps | alpha+dct ----------------
__global__ void __launch_bounds__(256) k_setup(const float* __restrict__ wav) {
    const int blk = blockIdx.x;
    const int tid = threadIdx.x;

    if (blk < PAD_BLKS) {
        int i = blk * 256 + tid;
        int q = i + (LEFT - PADR);
        int idx = (q < 0) ? -q : ((q >= NWAV) ? (2 * NWAV - 2 - q) : q);
        idx = max(0, min(idx, NWAV - 1));
        g_xw[i] = wav[idx];
        return;
    }
    if (blk < PAD_BLKS + E_BLKS) {
        int fi = (blk - PAD_BLKS) * 2 + (tid >> 7);
        int r  = tid & 127;
        int bi = fi / 3, j = fi % 3;
        int b  = bin_of(bi);
        float fb = (float)((b * r) & 65535) * (1.0f / 65536.0f);
        float fs = (float)r * (1.0f / (float)MW);
        float fr = fb + ((j == 1) ? -fs : (j == 2) ? fs : 0.0f);
        float s, c;
        sincospif(2.0f * fr, &s, &c);
        float re = c, im = -s;
        g_e[r * ECOLS + 2 * fi]     = re;
        g_e[r * ECOLS + 2 * fi + 1] = im;
        float rp = (r < 59) ? re : 0.0f;
        float ip = (r < 59) ? im : 0.0f;
        g_e[r * ECOLS + 1152 + 2 * fi]     = rp;
        g_e[r * ECOLS + 1152 + 2 * fi + 1] = ip;
        return;
    }
    if (blk < PAD_BLKS + E_BLKS + W_BLKS) {
        int lin = (blk - PAD_BLKS - E_BLKS) * 256 + tid;
        if (lin >= W_ELEMS) return;
        int fi = lin / WROWS;
        int u  = lin % WROWS;
        float wre = 0.0f, wim = 0.0f;
        if (u < 130 || u == 136) {
            int ue = (u == 136) ? 130 : u;
            int bi = fi / 3, j = fi % 3;
            int b  = bin_of(bi);
            float coeff = (j == 0) ? 0.5f : -0.25f;
            float fa = (float)((b * ue) & 511) * (1.0f / 512.0f);
            float fbv = (float)(128 * ue) * (1.0f / (float)MW);   // 128*130 < MW
            float fr = fa + ((j == 1) ? -fbv : (j == 2) ? fbv : 0.0f);
            float s, c;
            sincospif(2.0f * fr, &s, &c);
            wre = coeff * c;
            wim = -coeff * s;
        }
        g_w[u * 1152 + 2 * fi]     = wre;
        g_w[u * 1152 + 2 * fi + 1] = wim;
        return;
    }
    // last block: alpha + dct
    if (tid < NB) {
        float cq   = 32.7f * exp2f((float)tid / 24.0f);
        float idxf = cq / 8000.0f * 32768.0f;
        int lo = (int)idxf;
        lo = max(0, min(lo, 32767));
        g_alpha[tid] = idxf - (float)lo;
    }
    for (int idx = tid; idx < NC * NB; idx += 256) {
        int c = idx / NB, n = idx % NB;
        g_dct[idx] = cospif((float)(c * (2 * n + 1)) / 192.0f);
    }
}

// ---------------- stage 1: G[s, col] = sum_{r<128} xw[128s + r] * E[r, col] ----------------
__global__ void __launch_bounds__(256) k_s1() {
    extern __shared__ float smem[];
    float* xs = smem;            // 8192 floats
    float* ts = smem + 8192;     // 128 x 64

    const int c0 = blockIdx.x * 64;
    const int s0 = blockIdx.y * 64;
    const int tid = threadIdx.x;
    const int cg = tid & 15;
    const int fg = tid >> 4;

    const float4* xsrc = (const float4*)(g_xw + s0 * 128);
    #pragma unroll
    for (int i = tid; i < 2048; i += 256)
        ((float4*)xs)[i] = xsrc[i];
    #pragma unroll
    for (int i = tid; i < 2048; i += 256) {
        int kk = i >> 4, c4 = i & 15;
        ((float4*)ts)[i] = *(const float4*)(g_e + kk * ECOLS + c0 + c4 * 4);
    }
    __syncthreads();

    unsigned long long acc[4][2] = {};
    #pragma unroll 4
    for (int kk0 = 0; kk0 < 128; kk0 += 4) {
        float4 af[4];
        #pragma unroll
        for (int r = 0; r < 4; r++)
            af[r] = *(const float4*)(xs + (fg * 4 + r) * 128 + kk0);
        #pragma unroll
        for (int k = 0; k < 4; k++) {
            ulonglong2 bb = *(const ulonglong2*)(ts + (kk0 + k) * 64 + cg * 4);
            #pragma unroll
            for (int r = 0; r < 4; r++) {
                unsigned long long ad = dup2(((const float*)&af[r])[k]);
                fma2(acc[r][0], ad, bb.x);
                fma2(acc[r][1], ad, bb.y);
            }
        }
    }

    #pragma unroll
    for (int r = 0; r < 4; r++) {
        int s = s0 + fg * 4 + r;
        ulonglong2 v;
        v.x = acc[r][0]; v.y = acc[r][1];
        *(ulonglong2*)(g_g + (size_t)s * ECOLS + c0 + cg * 4) = v;
    }
}

// ---------------- stage 2: sliding-window complex FIR, FFMA2 ----------------
#define GS_STR 267    // float2 row stride for Gs (odd vs 32 banks)
#define GP_STR 133
__global__ void __launch_bounds__(256) k_s2() {
    extern __shared__ float smem[];
    float2* Gs = (float2*)smem;              // [16][GS_STR], rows 0..262 used
    float2* Gp = Gs + 16 * GS_STR;           // [16][GP_STR], rows 0..127 used
    float2* Ws = Gp + 16 * GP_STR;           // [137][16]

    const int fc0 = blockIdx.x * FTILE;
    const int t0  = blockIdx.y * TTILE;
    const int tid = threadIdx.x;

    for (int idx = tid; idx < 263 * 8; idx += 256) {
        int row = idx >> 3, p = idx & 7;
        float4 v = *(const float4*)(g_g + (size_t)(t0 + row) * ECOLS + fc0 * 2 + p * 4);
        Gs[(2 * p) * GS_STR + row]     = make_float2(v.x, v.y);
        Gs[(2 * p + 1) * GS_STR + row] = make_float2(v.z, v.w);
    }
    for (int idx = tid; idx < 128 * 8; idx += 256) {
        int row = idx >> 3, p = idx & 7;
        float4 v = *(const float4*)(g_g + (size_t)(t0 + 130 + row) * ECOLS + 1152 + fc0 * 2 + p * 4);
        Gp[(2 * p) * GP_STR + row]     = make_float2(v.x, v.y);
        Gp[(2 * p + 1) * GP_STR + row] = make_float2(v.z, v.w);
    }
    for (int idx = tid; idx < WROWS * 8; idx += 256) {
        int u = idx >> 3, p = idx & 7;
        float4 v = *(const float4*)(g_w + u * 1152 + fc0 * 2 + p * 4);
        Ws[u * 16 + 2 * p]     = make_float2(v.x, v.y);
        Ws[u * 16 + 2 * p + 1] = make_float2(v.z, v.w);
    }
    __syncthreads();

    const int f  = tid & 15;
    const int tg = tid >> 4;
    const int base = tg * 8;
    const float2* gb = Gs + f * GS_STR;

    unsigned long long acc[8] = {};
    unsigned long long gw[8], gsw[8];
    #pragma unroll
    for (int i = 0; i < 7; i++) {
        float2 g = gb[base + i];
        gw[i]  = pk2(g.x, g.y);
        gsw[i] = pk2(-g.y, g.x);
    }

    for (int uc = 0; uc < 136; uc += 8) {
        #pragma unroll
        for (int k = 0; k < 8; k++) {
            const int u = uc + k;
            {   // load row base+u+7 into slot (k+7)&7
                float2 g = gb[base + u + 7];
                gw[(k + 7) & 7]  = pk2(g.x, g.y);
                gsw[(k + 7) & 7] = pk2(-g.y, g.x);
            }
            float2 wt = Ws[u * 16 + f];
            unsigned long long wx = dup2(wt.x);
            unsigned long long wy = dup2(wt.y);
            #pragma unroll
            for (int r = 0; r < 8; r++) {
                fma2(acc[r], wx, gw[(k + r) & 7]);
                fma2(acc[r], wy, gsw[(k + r) & 7]);
            }
        }
    }
    {   // partial segment tap (stored at row 136) against Gp
        float2 wt = Ws[136 * 16 + f];
        unsigned long long wx = dup2(wt.x);
        unsigned long long wy = dup2(wt.y);
        const float2* gp = Gp + f * GP_STR + base;
        #pragma unroll
        for (int r = 0; r < 8; r++) {
            float2 g = gp[r];
            fma2(acc[r], wx, pk2(g.x, g.y));
            fma2(acc[r], wy, pk2(-g.y, g.x));
        }
    }

    #pragma unroll
    for (int r = 0; r < 8; r++) {
        int t = t0 + base + r;
        *(float2*)(g_z + (size_t)t * 1152 + (fc0 + f) * 2) = upk2(acc[r]);
    }
}

// ---------------- combine triples -> power -> lerp -> log -> DCT ----------------
__global__ void k_ceps() {
    int t = blockIdx.x;
    __shared__ float sp[NB];
    int f = threadIdx.x;  // 96 threads
    const float* zr = g_z + (size_t)t * 1152 + 12 * f;
    float4 a = *(const float4*)(zr);
    float4 b = *(const float4*)(zr + 4);
    float4 c = *(const float4*)(zr + 8);
    float lre = a.x + a.z + b.x, lim = a.y + a.w + b.y;
    float hre = b.z + c.x + c.z, him = b.w + c.y + c.w;
    float plo = lre * lre + lim * lim;
    float phi = hre * hre + him * him;
    float al = g_alpha[f];
    float p = (1.0f - al) * plo + al * phi;
    sp[f] = logf(fmaxf(p, 1e-8f));
    __syncthreads();
    if (f < NC) {
        float s = 0.0f;
        #pragma unroll 8
        for (int n = 0; n < NB; n++) s += sp[n] * g_dct[f * NB + n];
        g_c[t * NC + f] = s;
    }
}

// ---------------- fused normalize + delta + delta-delta ----------------
__global__ void __launch_bounds__(256) k_tail(float* __restrict__ out) {
    const int c = blockIdx.x;       // 0..19
    const int tid = threadIdx.x;
    __shared__ float cn[T_FRAMES];
    __shared__ float d1s[T_FRAMES];
    __shared__ float red[256];

    float s = 0.0f;
    for (int t = tid; t < T_FRAMES; t += 256) {
        float v = g_c[t * NC + c];
        cn[t] = v;
        s += v;
    }
    red[tid] = s; __syncthreads();
    for (int o = 128; o; o >>= 1) { if (tid < o) red[tid] += red[tid + o]; __syncthreads(); }
    float mean = red[0] / (float)T_FRAMES;
    __syncthreads();
    float ss = 0.0f;
    for (int t = tid; t < T_FRAMES; t += 256) { float d = cn[t] - mean; ss += d * d; }
    red[tid] = ss; __syncthreads();
    for (int o = 128; o; o >>= 1) { if (tid < o) red[tid] += red[tid + o]; __syncthreads(); }
    float inv = 1.0f / (sqrtf(red[0] / (float)(T_FRAMES - 1)) + 1e-8f);
    __syncthreads();
    for (int t = tid; t < T_FRAMES; t += 256) cn[t] = (cn[t] - mean) * inv;
    __syncthreads();

    for (int t = tid; t < T_FRAMES; t += 256) {
        int tp1 = min(t + 1, T_FRAMES - 1), tm1 = max(t - 1, 0);
        int tp2 = min(t + 2, T_FRAMES - 1), tm2 = max(t - 2, 0);
        float d = ((cn[tp1] - cn[tm1]) + 2.0f * (cn[tp2] - cn[tm2])) * 0.1f;
        d1s[t] = d;
        out[t * 60 + c]      = cn[t];
        out[t * 60 + 20 + c] = d;
    }
    __syncthreads();
    for (int t = tid; t < T_FRAMES; t += 256) {
        int tp1 = min(t + 1, T_FRAMES - 1), tm1 = max(t - 1, 0);
        int tp2 = min(t + 2, T_FRAMES - 1), tm2 = max(t - 2, 0);
        float d = ((d1s[tp1] - d1s[tm1]) + 2.0f * (d1s[tp2] - d1s[tm2])) * 0.1f;
        out[t * 60 + 40 + c] = d;
    }
}

// ---------------- launch ----------------
extern "C" void kernel_launch(void* const* d_in, const int* in_sizes, int n_in,
                              void* d_out, int out_size) {
    const float* wav = (const float*)d_in[0];
    float* out = (float*)d_out;

    const int s1_smem = 65536;
    const int s2_smem = (16 * GS_STR + 16 * GP_STR + WROWS * 16) * 8;  // 68736
    cudaFuncSetAttribute(k_s1, cudaFuncAttributeMaxDynamicSharedMemorySize, s1_smem);
    cudaFuncSetAttribute(k_s2, cudaFuncAttributeMaxDynamicSharedMemorySize, s2_smem);

    k_setup<<<SETUP_BLKS, 256>>>(wav);
    k_s1<<<dim3(ECOLS / 64, SROWS / 64), 256, s1_smem>>>();
    k_s2<<<dim3(FT, TT), 256, s2_smem>>>();
    k_ceps<<<T_FRAMES, 96>>>();
    k_tail<<<NC, 256>>>(out);
}

// round 7
// speedup vs baseline: 13.5461x; 1.2291x over previous
#include <cuda_runtime.h>
#include <cstdint>

// ---------------- constants ----------------
#define T_FRAMES 2049
#define NWAV     262144
#define MW       16699
#define LEFT     24418
#define PADR     32768
#define NB       96
#define NC       20
#define NF       576            // 192 bins x 3 sub-frequencies
#define ECOLS    2304           // [full 1152 | partial 1152]
#define GROWS    2368
#define XW_LEN   294912         // 2304*128
#define TTILE    128
#define TT       17
#define ZROWST   2176
#define FTILE    16
#define FT       36
#define WROWS    137            // 0..129 full taps, 130..135 zero, 136 partial tap

// setup kernel block ranges
#define PAD_BLKS 1152           // 294912/256
#define E_BLKS   288            // 2 fi per block
#define W_ELEMS  (NF * WROWS)   // 78912
#define W_BLKS   309
#define SETUP_BLKS (PAD_BLKS + E_BLKS + W_BLKS + 1)

// ---------------- device scratch ----------------
__device__ float g_xw[XW_LEN];
__device__ float g_e[128 * ECOLS];
__device__ float g_w[WROWS * 1152];
__device__ float g_g[(size_t)GROWS * ECOLS];
__device__ float g_z[(size_t)ZROWST * 1152];
__device__ float g_c[T_FRAMES * NC];
__device__ float g_alpha[NB];
__device__ float g_dct[NC * NB];

// ---------------- f32x2 helpers ----------------
__device__ __forceinline__ void fma2(unsigned long long& acc,
                                     unsigned long long a, unsigned long long b) {
    asm("fma.rn.f32x2 %0, %1, %2, %0;" : "+l"(acc) : "l"(a), "l"(b));
}
__device__ __forceinline__ unsigned long long dup2(float x) {
    unsigned long long r;
    asm("mov.b64 %0, {%1, %1};" : "=l"(r) : "f"(x));
    return r;
}
__device__ __forceinline__ unsigned long long pk2(float x, float y) {
    unsigned long long r;
    asm("mov.b64 %0, {%1, %2};" : "=l"(r) : "f"(x), "f"(y));
    return r;
}
__device__ __forceinline__ float2 upk2(unsigned long long v) {
    float2 r;
    asm("mov.b64 {%0, %1}, %2;" : "=f"(r.x), "=f"(r.y) : "l"(v));
    return r;
}

// ---------------- inline bin computation ----------------
__device__ __forceinline__ int bin_of(int bi) {   // bi 0..191
    int i = bi >> 1;
    float cq   = 32.7f * exp2f((float)i / 24.0f);
    float idxf = cq / 8000.0f * 32768.0f;
    int lo = (int)idxf;
    lo = max(0, min(lo, 32767));
    return lo + (bi & 1);
}

// ---------------- fused setup: pad | stage-1 basis | stage-2 taps | alpha+dct ----------------
__global__ void __launch_bounds__(256) k_setup(const float* __restrict__ wav) {
    const int blk = blockIdx.x;
    const int tid = threadIdx.x;

    if (blk < PAD_BLKS) {
        int i = blk * 256 + tid;
        int q = i + (LEFT - PADR);
        int idx = (q < 0) ? -q : ((q >= NWAV) ? (2 * NWAV - 2 - q) : q);
        idx = max(0, min(idx, NWAV - 1));
        g_xw[i] = wav[idx];
        return;
    }
    if (blk < PAD_BLKS + E_BLKS) {
        int fi = (blk - PAD_BLKS) * 2 + (tid >> 7);
        int r  = tid & 127;
        int bi = fi / 3, j = fi % 3;
        int b  = bin_of(bi);
        float fb = (float)((b * r) & 65535) * (1.0f / 65536.0f);
        float fs = (float)r * (1.0f / (float)MW);
        float fr = fb + ((j == 1) ? -fs : (j == 2) ? fs : 0.0f);
        float s, c;
        sincospif(2.0f * fr, &s, &c);
        float re = c, im = -s;
        g_e[r * ECOLS + 2 * fi]     = re;
        g_e[r * ECOLS + 2 * fi + 1] = im;
        float rp = (r < 59) ? re : 0.0f;
        float ip = (r < 59) ? im : 0.0f;
        g_e[r * ECOLS + 1152 + 2 * fi]     = rp;
        g_e[r * ECOLS + 1152 + 2 * fi + 1] = ip;
        return;
    }
    if (blk < PAD_BLKS + E_BLKS + W_BLKS) {
        int lin = (blk - PAD_BLKS - E_BLKS) * 256 + tid;
        if (lin >= W_ELEMS) return;
        int fi = lin / WROWS;
        int u  = lin % WROWS;
        float wre = 0.0f, wim = 0.0f;
        if (u < 130 || u == 136) {
            int ue = (u == 136) ? 130 : u;
            int bi = fi / 3, j = fi % 3;
            int b  = bin_of(bi);
            float coeff = (j == 0) ? 0.5f : -0.25f;
            float fa = (float)((b * ue) & 511) * (1.0f / 512.0f);
            float fbv = (float)(128 * ue) * (1.0f / (float)MW);
            float fr = fa + ((j == 1) ? -fbv : (j == 2) ? fbv : 0.0f);
            float s, c;
            sincospif(2.0f * fr, &s, &c);
            wre = coeff * c;
            wim = -coeff * s;
        }
        g_w[u * 1152 + 2 * fi]     = wre;
        g_w[u * 1152 + 2 * fi + 1] = wim;
        return;
    }
    // last block: alpha + dct
    if (tid < NB) {
        float cq   = 32.7f * exp2f((float)tid / 24.0f);
        float idxf = cq / 8000.0f * 32768.0f;
        int lo = (int)idxf;
        lo = max(0, min(lo, 32767));
        g_alpha[tid] = idxf - (float)lo;
    }
    for (int idx = tid; idx < NC * NB; idx += 256) {
        int c = idx / NB, n = idx % NB;
        g_dct[idx] = cospif((float)(c * (2 * n + 1)) / 192.0f);
    }
}

// ---------------- stage 1: G[s, col] = sum_r xw[128s + r] * E[r, col] ----------------
// block 128 rows x 64 cols; thread tile 8x4; partial-col blocks run K=64.
__global__ void __launch_bounds__(256) k_s1() {
    extern __shared__ float smem[];
    float* xs = smem;            // 16384 floats (64 KB)
    float* ts = smem + 16384;    // up to 128 x 64 (32 KB)

    const int bx = blockIdx.x;                 // 0..35
    const int c0 = bx * 64;
    const int K  = (bx < 18) ? 128 : 64;       // partial basis zero for r>=59
    const int s0 = blockIdx.y * 128;
    const int tid = threadIdx.x;
    const int cg = tid & 15;
    const int fg = tid >> 4;

    const float4* xsrc = (const float4*)(g_xw + s0 * 128);
    #pragma unroll
    for (int i = tid; i < 4096; i += 256)
        ((float4*)xs)[i] = xsrc[i];
    for (int i = tid; i < K * 16; i += 256) {
        int kk = i >> 4, c4 = i & 15;
        ((float4*)ts)[i] = *(const float4*)(g_e + kk * ECOLS + c0 + c4 * 4);
    }
    __syncthreads();

    unsigned long long acc[8][2] = {};
    for (int kk0 = 0; kk0 < K; kk0 += 4) {
        float4 af[8];
        #pragma unroll
        for (int r = 0; r < 8; r++)
            af[r] = *(const float4*)(xs + (fg * 8 + r) * 128 + kk0);
        #pragma unroll
        for (int k = 0; k < 4; k++) {
            ulonglong2 bb = *(const ulonglong2*)(ts + (kk0 + k) * 64 + cg * 4);
            #pragma unroll
            for (int r = 0; r < 8; r++) {
                unsigned long long ad = dup2(((const float*)&af[r])[k]);
                fma2(acc[r][0], ad, bb.x);
                fma2(acc[r][1], ad, bb.y);
            }
        }
    }

    #pragma unroll
    for (int r = 0; r < 8; r++) {
        int s = s0 + fg * 8 + r;
        ulonglong2 v;
        v.x = acc[r][0]; v.y = acc[r][1];
        *(ulonglong2*)(g_g + (size_t)s * ECOLS + c0 + cg * 4) = v;
    }
}

// ---------------- stage 2: sliding-window complex FIR, FFMA2 ----------------
#define GS_STR 267
#define GP_STR 133
__global__ void __launch_bounds__(256) k_s2() {
    extern __shared__ float smem[];
    float2* Gs = (float2*)smem;              // [16][GS_STR]
    float2* Gp = Gs + 16 * GS_STR;           // [16][GP_STR]
    float2* Ws = Gp + 16 * GP_STR;           // [137][16]

    const int fc0 = blockIdx.x * FTILE;
    const int t0  = blockIdx.y * TTILE;
    const int tid = threadIdx.x;

    for (int idx = tid; idx < 263 * 8; idx += 256) {
        int row = idx >> 3, p = idx & 7;
        float4 v = *(const float4*)(g_g + (size_t)(t0 + row) * ECOLS + fc0 * 2 + p * 4);
        Gs[(2 * p) * GS_STR + row]     = make_float2(v.x, v.y);
        Gs[(2 * p + 1) * GS_STR + row] = make_float2(v.z, v.w);
    }
    for (int idx = tid; idx < 128 * 8; idx += 256) {
        int row = idx >> 3, p = idx & 7;
        float4 v = *(const float4*)(g_g + (size_t)(t0 + 130 + row) * ECOLS + 1152 + fc0 * 2 + p * 4);
        Gp[(2 * p) * GP_STR + row]     = make_float2(v.x, v.y);
        Gp[(2 * p + 1) * GP_STR + row] = make_float2(v.z, v.w);
    }
    for (int idx = tid; idx < WROWS * 8; idx += 256) {
        int u = idx >> 3, p = idx & 7;
        float4 v = *(const float4*)(g_w + u * 1152 + fc0 * 2 + p * 4);
        Ws[u * 16 + 2 * p]     = make_float2(v.x, v.y);
        Ws[u * 16 + 2 * p + 1] = make_float2(v.z, v.w);
    }
    __syncthreads();

    const int f  = tid & 15;
    const int tg = tid >> 4;
    const int base = tg * 8;
    const float2* gb = Gs + f * GS_STR;

    unsigned long long acc[8] = {};
    unsigned long long gw[8], gsw[8];
    #pragma unroll
    for (int i = 0; i < 7; i++) {
        float2 g = gb[base + i];
        gw[i]  = pk2(g.x, g.y);
        gsw[i] = pk2(-g.y, g.x);
    }

    for (int uc = 0; uc < 136; uc += 8) {
        #pragma unroll
        for (int k = 0; k < 8; k++) {
            const int u = uc + k;
            {
                float2 g = gb[base + u + 7];
                gw[(k + 7) & 7]  = pk2(g.x, g.y);
                gsw[(k + 7) & 7] = pk2(-g.y, g.x);
            }
            float2 wt = Ws[u * 16 + f];
            unsigned long long wx = dup2(wt.x);
            unsigned long long wy = dup2(wt.y);
            #pragma unroll
            for (int r = 0; r < 8; r++) {
                fma2(acc[r], wx, gw[(k + r) & 7]);
                fma2(acc[r], wy, gsw[(k + r) & 7]);
            }
        }
    }
    {
        float2 wt = Ws[136 * 16 + f];
        unsigned long long wx = dup2(wt.x);
        unsigned long long wy = dup2(wt.y);
        const float2* gp = Gp + f * GP_STR + base;
        #pragma unroll
        for (int r = 0; r < 8; r++) {
            float2 g = gp[r];
            fma2(acc[r], wx, pk2(g.x, g.y));
            fma2(acc[r], wy, pk2(-g.y, g.x));
        }
    }

    #pragma unroll
    for (int r = 0; r < 8; r++) {
        int t = t0 + base + r;
        *(float2*)(g_z + (size_t)t * 1152 + (fc0 + f) * 2) = upk2(acc[r]);
    }
}

// ---------------- ceps: 8 frames per block, warp per frame ----------------
__global__ void __launch_bounds__(256) k_ceps() {
    __shared__ float dcts[NB * NC];       // transposed: [n][c]
    __shared__ float sp[8][NB];
    const int tid = threadIdx.x;
    const int w = tid >> 5, l = tid & 31;
    const int fr = blockIdx.x * 8 + w;

    for (int i = tid; i < NB * NC; i += 256) {
        int n = i / NC, c = i % NC;
        dcts[i] = g_dct[c * NB + n];
    }

    if (fr < T_FRAMES) {
        const float* zr = g_z + (size_t)fr * 1152 + l * 36;
        float a[36];
        #pragma unroll
        for (int i = 0; i < 9; i++)
            ((float4*)a)[i] = ((const float4*)zr)[i];
        #pragma unroll
        for (int k = 0; k < 3; k++) {
            const int off = 12 * k;
            int bin = 3 * l + k;
            float lre = a[off] + a[off + 2] + a[off + 4];
            float lim = a[off + 1] + a[off + 3] + a[off + 5];
            float hre = a[off + 6] + a[off + 8] + a[off + 10];
            float him = a[off + 7] + a[off + 9] + a[off + 11];
            float plo = lre * lre + lim * lim;
            float phi = hre * hre + him * him;
            float al = g_alpha[bin];
            float p = (1.0f - al) * plo + al * phi;
            sp[w][bin] = logf(fmaxf(p, 1e-8f));
        }
    }
    __syncthreads();
    if (fr < T_FRAMES && l < NC) {
        float s = 0.0f;
        #pragma unroll 8
        for (int n = 0; n < NB; n++) s = fmaf(sp[w][n], dcts[n * NC + l], s);
        g_c[fr * NC + l] = s;
    }
}

// ---------------- fused normalize + delta + delta-delta ----------------
__global__ void __launch_bounds__(256) k_tail(float* __restrict__ out) {
    const int c = blockIdx.x;       // 0..19
    const int tid = threadIdx.x;
    __shared__ float cn[T_FRAMES];
    __shared__ float d1s[T_FRAMES];
    __shared__ float red[256];

    float s = 0.0f;
    for (int t = tid; t < T_FRAMES; t += 256) {
        float v = g_c[t * NC + c];
        cn[t] = v;
        s += v;
    }
    red[tid] = s; __syncthreads();
    for (int o = 128; o; o >>= 1) { if (tid < o) red[tid] += red[tid + o]; __syncthreads(); }
    float mean = red[0] / (float)T_FRAMES;
    __syncthreads();
    float ss = 0.0f;
    for (int t = tid; t < T_FRAMES; t += 256) { float d = cn[t] - mean; ss += d * d; }
    red[tid] = ss; __syncthreads();
    for (int o = 128; o; o >>= 1) { if (tid < o) red[tid] += red[tid + o]; __syncthreads(); }
    float inv = 1.0f / (sqrtf(red[0] / (float)(T_FRAMES - 1)) + 1e-8f);
    __syncthreads();
    for (int t = tid; t < T_FRAMES; t += 256) cn[t] = (cn[t] - mean) * inv;
    __syncthreads();

    for (int t = tid; t < T_FRAMES; t += 256) {
        int tp1 = min(t + 1, T_FRAMES - 1), tm1 = max(t - 1, 0);
        int tp2 = min(t + 2, T_FRAMES - 1), tm2 = max(t - 2, 0);
        float d = ((cn[tp1] - cn[tm1]) + 2.0f * (cn[tp2] - cn[tm2])) * 0.1f;
        d1s[t] = d;
        out[t * 60 + c]      = cn[t];
        out[t * 60 + 20 + c] = d;
    }
    __syncthreads();
    for (int t = tid; t < T_FRAMES; t += 256) {
        int tp1 = min(t + 1, T_FRAMES - 1), tm1 = max(t - 1, 0);
        int tp2 = min(t + 2, T_FRAMES - 1), tm2 = max(t - 2, 0);
        float d = ((d1s[tp1] - d1s[tm1]) + 2.0f * (d1s[tp2] - d1s[tm2])) * 0.1f;
        out[t * 60 + 40 + c] = d;
    }
}

// ---------------- launch ----------------
extern "C" void kernel_launch(void* const* d_in, const int* in_sizes, int n_in,
                              void* d_out, int out_size) {
    const float* wav = (const float*)d_in[0];
    float* out = (float*)d_out;

    const int s1_smem = (16384 + 128 * 64) * 4;   // 98304
    const int s2_smem = (16 * GS_STR + 16 * GP_STR + WROWS * 16) * 8;  // 68736
    cudaFuncSetAttribute(k_s1, cudaFuncAttributeMaxDynamicSharedMemorySize, s1_smem);
    cudaFuncSetAttribute(k_s2, cudaFuncAttributeMaxDynamicSharedMemorySize, s2_smem);

    k_setup<<<SETUP_BLKS, 256>>>(wav);
    k_s1<<<dim3(36, 18), 256, s1_smem>>>();
    k_s2<<<dim3(FT, TT), 256, s2_smem>>>();
    k_ceps<<<257, 256>>>();
    k_tail<<<NC, 256>>>(out);
}

// round 8
// speedup vs baseline: 14.2063x; 1.0487x over previous
#include <cuda_runtime.h>
#include <cstdint>

// ---------------- constants ----------------
#define T_FRAMES 2049
#define NWAV     262144
#define MW       16699
#define LEFT     24418
#define PADR     32768
#define NB       96
#define NC       20
#define NF       576            // 192 bins x 3 sub-frequencies
#define ECOLS    2304           // [full 1152 | partial 1152]
#define GROWS    2368
#define XW_LEN   294912         // 2304*128
#define WROWS    137            // 0..129 full taps, 130..135 zero, 136 partial tap

// stage-2 tiling: 18 complex freqs (=3 cqt bins) x 112 frames
#define FTILE2   18
#define TTILE2   112
#define TT2      19             // 19*112 = 2128 >= 2049
#define FB2      32             // 576/18
#define GS_STR   249            // float2 stride, rows 0..246
#define GP_STR   113            // float2 stride, rows 0..111 (reused for Zs)

// setup kernel block ranges
#define PAD_BLKS 1152           // 294912/256
#define E_BLKS   288
#define W_ELEMS  (NF * WROWS)
#define W_BLKS   309
#define SETUP_BLKS (PAD_BLKS + E_BLKS + W_BLKS + 1)

// ---------------- device scratch ----------------
__device__ float g_xw[XW_LEN];
__device__ float g_e[128 * ECOLS];
__device__ float g_w[WROWS * 1152];
__device__ float g_g[(size_t)GROWS * ECOLS];
__device__ float g_lp[(size_t)T_FRAMES * NB];   // log cqt power
__device__ float g_c[T_FRAMES * NC];
__device__ float g_alpha[NB];
__device__ float g_dct[NC * NB];

// ---------------- f32x2 helpers ----------------
__device__ __forceinline__ void fma2(unsigned long long& acc,
                                     unsigned long long a, unsigned long long b) {
    asm("fma.rn.f32x2 %0, %1, %2, %0;" : "+l"(acc) : "l"(a), "l"(b));
}
__device__ __forceinline__ unsigned long long dup2(float x) {
    unsigned long long r;
    asm("mov.b64 %0, {%1, %1};" : "=l"(r) : "f"(x));
    return r;
}
__device__ __forceinline__ unsigned long long pk2(float x, float y) {
    unsigned long long r;
    asm("mov.b64 %0, {%1, %2};" : "=l"(r) : "f"(x), "f"(y));
    return r;
}
__device__ __forceinline__ float2 upk2(unsigned long long v) {
    float2 r;
    asm("mov.b64 {%0, %1}, %2;" : "=f"(r.x), "=f"(r.y) : "l"(v));
    return r;
}

// ---------------- inline bin computation ----------------
__device__ __forceinline__ int bin_of(int bi) {   // bi 0..191
    int i = bi >> 1;
    float cq   = 32.7f * exp2f((float)i / 24.0f);
    float idxf = cq / 8000.0f * 32768.0f;
    int lo = (int)idxf;
    lo = max(0, min(lo, 32767));
    return lo + (bi & 1);
}

// ---------------- fused setup: pad | stage-1 basis | stage-2 taps | alpha+dct ----------------
__global__ void __launch_bounds__(256) k_setup(const float* __restrict__ wav) {
    const int blk = blockIdx.x;
    const int tid = threadIdx.x;

    if (blk < PAD_BLKS) {
        int i = blk * 256 + tid;
        int q = i + (LEFT - PADR);
        int idx = (q < 0) ? -q : ((q >= NWAV) ? (2 * NWAV - 2 - q) : q);
        idx = max(0, min(idx, NWAV - 1));
        g_xw[i] = wav[idx];
        return;
    }
    if (blk < PAD_BLKS + E_BLKS) {
        int fi = (blk - PAD_BLKS) * 2 + (tid >> 7);
        int r  = tid & 127;
        int bi = fi / 3, j = fi % 3;
        int b  = bin_of(bi);
        float fb = (float)((b * r) & 65535) * (1.0f / 65536.0f);
        float fs = (float)r * (1.0f / (float)MW);
        float fr = fb + ((j == 1) ? -fs : (j == 2) ? fs : 0.0f);
        float s, c;
        sincospif(2.0f * fr, &s, &c);
        float re = c, im = -s;
        g_e[r * ECOLS + 2 * fi]     = re;
        g_e[r * ECOLS + 2 * fi + 1] = im;
        float rp = (r < 59) ? re : 0.0f;
        float ip = (r < 59) ? im : 0.0f;
        g_e[r * ECOLS + 1152 + 2 * fi]     = rp;
        g_e[r * ECOLS + 1152 + 2 * fi + 1] = ip;
        return;
    }
    if (blk < PAD_BLKS + E_BLKS + W_BLKS) {
        int lin = (blk - PAD_BLKS - E_BLKS) * 256 + tid;
        if (lin >= W_ELEMS) return;
        int fi = lin / WROWS;
        int u  = lin % WROWS;
        float wre = 0.0f, wim = 0.0f;
        if (u < 130 || u == 136) {
            int ue = (u == 136) ? 130 : u;
            int bi = fi / 3, j = fi % 3;
            int b  = bin_of(bi);
            float coeff = (j == 0) ? 0.5f : -0.25f;
            float fa = (float)((b * ue) & 511) * (1.0f / 512.0f);
            float fbv = (float)(128 * ue) * (1.0f / (float)MW);
            float fr = fa + ((j == 1) ? -fbv : (j == 2) ? fbv : 0.0f);
            float s, c;
            sincospif(2.0f * fr, &s, &c);
            wre = coeff * c;
            wim = -coeff * s;
        }
        g_w[u * 1152 + 2 * fi]     = wre;
        g_w[u * 1152 + 2 * fi + 1] = wim;
        return;
    }
    // last block: alpha + dct
    if (tid < NB) {
        float cq   = 32.7f * exp2f((float)tid / 24.0f);
        float idxf = cq / 8000.0f * 32768.0f;
        int lo = (int)idxf;
        lo = max(0, min(lo, 32767));
        g_alpha[tid] = idxf - (float)lo;
    }
    for (int idx = tid; idx < NC * NB; idx += 256) {
        int c = idx / NB, n = idx % NB;
        g_dct[idx] = cospif((float)(c * (2 * n + 1)) / 192.0f);
    }
}

// ---------------- stage 1: G[s, col] = sum_r xw[128s + r] * E[r, col] ----------------
// block 128 rows x 64 cols; thread tile 8x4; partial-col blocks run K=64.
__global__ void __launch_bounds__(256) k_s1() {
    extern __shared__ float smem[];
    float* xs = smem;            // 16384 floats
    float* ts = smem + 16384;    // up to 128 x 64

    const int bx = blockIdx.x;                 // 0..35
    const int c0 = bx * 64;
    const int K  = (bx < 18) ? 128 : 64;
    const int s0 = blockIdx.y * 128;
    const int tid = threadIdx.x;
    const int cg = tid & 15;
    const int fg = tid >> 4;

    const float4* xsrc = (const float4*)(g_xw + s0 * 128);
    #pragma unroll
    for (int i = tid; i < 4096; i += 256)
        ((float4*)xs)[i] = xsrc[i];
    for (int i = tid; i < K * 16; i += 256) {
        int kk = i >> 4, c4 = i & 15;
        ((float4*)ts)[i] = *(const float4*)(g_e + kk * ECOLS + c0 + c4 * 4);
    }
    __syncthreads();

    unsigned long long acc[8][2] = {};
    for (int kk0 = 0; kk0 < K; kk0 += 4) {
        float4 af[8];
        #pragma unroll
        for (int r = 0; r < 8; r++)
            af[r] = *(const float4*)(xs + (fg * 8 + r) * 128 + kk0);
        #pragma unroll
        for (int k = 0; k < 4; k++) {
            ulonglong2 bb = *(const ulonglong2*)(ts + (kk0 + k) * 64 + cg * 4);
            #pragma unroll
            for (int r = 0; r < 8; r++) {
                unsigned long long ad = dup2(((const float*)&af[r])[k]);
                fma2(acc[r][0], ad, bb.x);
                fma2(acc[r][1], ad, bb.y);
            }
        }
    }

    #pragma unroll
    for (int r = 0; r < 8; r++) {
        int s = s0 + fg * 8 + r;
        ulonglong2 v;
        v.x = acc[r][0]; v.y = acc[r][1];
        *(ulonglong2*)(g_g + (size_t)s * ECOLS + c0 + cg * 4) = v;
    }
}

// ---------------- stage 2: sliding-window complex FIR + fused power/log ----------------
// block: 112 frames x 18 complex freqs (3 cqt bins). 252 compute threads.
__global__ void __launch_bounds__(256) k_s2() {
    extern __shared__ float smem[];
    float2* Gs = (float2*)smem;               // [18][GS_STR], rows 0..246
    float2* Gp = Gs + FTILE2 * GS_STR;        // [18][GP_STR], rows 0..111 (later Zs)
    float2* Ws = Gp + FTILE2 * GP_STR;        // [137][18]

    const int m   = blockIdx.x;               // bin-triple index 0..31
    const int fc0 = m * FTILE2;
    const int t0  = blockIdx.y * TTILE2;
    const int tid = threadIdx.x;

    for (int idx = tid; idx < 247 * 9; idx += 256) {
        int row = idx / 9, p = idx % 9;
        float4 v = *(const float4*)(g_g + (size_t)(t0 + row) * ECOLS + fc0 * 2 + p * 4);
        Gs[(2 * p) * GS_STR + row]     = make_float2(v.x, v.y);
        Gs[(2 * p + 1) * GS_STR + row] = make_float2(v.z, v.w);
    }
    for (int idx = tid; idx < 112 * 9; idx += 256) {
        int row = idx / 9, p = idx % 9;
        float4 v = *(const float4*)(g_g + (size_t)(t0 + 130 + row) * ECOLS + 1152 + fc0 * 2 + p * 4);
        Gp[(2 * p) * GP_STR + row]     = make_float2(v.x, v.y);
        Gp[(2 * p + 1) * GP_STR + row] = make_float2(v.z, v.w);
    }
    for (int idx = tid; idx < WROWS * 9; idx += 256) {
        int u = idx / 9, p = idx % 9;
        float4 v = *(const float4*)(g_w + u * 1152 + fc0 * 2 + p * 4);
        Ws[u * FTILE2 + 2 * p]     = make_float2(v.x, v.y);
        Ws[u * FTILE2 + 2 * p + 1] = make_float2(v.z, v.w);
    }
    __syncthreads();

    const int f  = tid % FTILE2;
    const int tg = tid / FTILE2;               // 0..13 valid
    const bool active = (tid < 252);
    const int base = tg * 8;
    const float2* gb = Gs + f * GS_STR;

    unsigned long long acc[8] = {};
    if (active) {
        unsigned long long gw[8], gsw[8];
        #pragma unroll
        for (int i = 0; i < 7; i++) {
            float2 g = gb[base + i];
            gw[i]  = pk2(g.x, g.y);
            gsw[i] = pk2(-g.y, g.x);
        }
        for (int uc = 0; uc < 136; uc += 8) {
            #pragma unroll
            for (int k = 0; k < 8; k++) {
                const int u = uc + k;
                {
                    float2 g = gb[base + u + 7];
                    gw[(k + 7) & 7]  = pk2(g.x, g.y);
                    gsw[(k + 7) & 7] = pk2(-g.y, g.x);
                }
                float2 wt = Ws[u * FTILE2 + f];
                unsigned long long wx = dup2(wt.x);
                unsigned long long wy = dup2(wt.y);
                #pragma unroll
                for (int r = 0; r < 8; r++) {
                    fma2(acc[r], wx, gw[(k + r) & 7]);
                    fma2(acc[r], wy, gsw[(k + r) & 7]);
                }
            }
        }
        {
            float2 wt = Ws[136 * FTILE2 + f];
            unsigned long long wx = dup2(wt.x);
            unsigned long long wy = dup2(wt.y);
            const float2* gp = Gp + f * GP_STR + base;
            #pragma unroll
            for (int r = 0; r < 8; r++) {
                float2 g = gp[r];
                fma2(acc[r], wx, pk2(g.x, g.y));
                fma2(acc[r], wy, pk2(-g.y, g.x));
            }
        }
    }
    __syncthreads();                           // Gp fully consumed; reuse as Zs
    float2* Zs = Gp;
    if (active) {
        #pragma unroll
        for (int r = 0; r < 8; r++)
            Zs[f * GP_STR + base + r] = upk2(acc[r]);
    }
    __syncthreads();

    // combine triples -> power -> lerp -> log for 3 cqt bins x 112 frames
    for (int idx = tid; idx < 3 * TTILE2; idx += 256) {
        int q  = idx / TTILE2;                 // local bin 0..2
        int tl = idx % TTILE2;
        int t  = t0 + tl;
        if (t >= T_FRAMES) continue;
        const float2* zq = Zs + (6 * q) * GP_STR + tl;
        float2 z0 = zq[0];
        float2 z1 = zq[GP_STR];
        float2 z2 = zq[2 * GP_STR];
        float2 z3 = zq[3 * GP_STR];
        float2 z4 = zq[4 * GP_STR];
        float2 z5 = zq[5 * GP_STR];
        float lre = z0.x + z1.x + z2.x, lim = z0.y + z1.y + z2.y;
        float hre = z3.x + z4.x + z5.x, him = z3.y + z4.y + z5.y;
        float plo = lre * lre + lim * lim;
        float phi = hre * hre + him * him;
        int bin = 3 * m + q;
        float al = g_alpha[bin];
        float p = (1.0f - al) * plo + al * phi;
        g_lp[(size_t)t * NB + bin] = logf(fmaxf(p, 1e-8f));
    }
}

// ---------------- ceps: DCT only (8 frames per block, warp per frame) ----------------
__global__ void __launch_bounds__(256) k_ceps() {
    __shared__ float dcts[NB * NC];           // transposed [n][c]
    __shared__ float sp[8][NB];
    const int tid = threadIdx.x;
    const int w = tid >> 5, l = tid & 31;
    const int fr = blockIdx.x * 8 + w;

    for (int i = tid; i < NB * NC; i += 256) {
        int n = i / NC, c = i % NC;
        dcts[i] = g_dct[c * NB + n];
    }
    if (fr < T_FRAMES) {
        #pragma unroll
        for (int k = 0; k < 3; k++)
            sp[w][l * 3 + k] = g_lp[(size_t)fr * NB + l * 3 + k];
    }
    __syncthreads();
    if (fr < T_FRAMES && l < NC) {
        float s = 0.0f;
        #pragma unroll 8
        for (int n = 0; n < NB; n++) s = fmaf(sp[w][n], dcts[n * NC + l], s);
        g_c[fr * NC + l] = s;
    }
}

// ---------------- fused normalize + delta + delta-delta ----------------
__global__ void __launch_bounds__(256) k_tail(float* __restrict__ out) {
    const int c = blockIdx.x;       // 0..19
    const int tid = threadIdx.x;
    __shared__ float cn[T_FRAMES];
    __shared__ float d1s[T_FRAMES];
    __shared__ float red[256];

    float s = 0.0f;
    for (int t = tid; t < T_FRAMES; t += 256) {
        float v = g_c[t * NC + c];
        cn[t] = v;
        s += v;
    }
    red[tid] = s; __syncthreads();
    for (int o = 128; o; o >>= 1) { if (tid < o) red[tid] += red[tid + o]; __syncthreads(); }
    float mean = red[0] / (float)T_FRAMES;
    __syncthreads();
    float ss = 0.0f;
    for (int t = tid; t < T_FRAMES; t += 256) { float d = cn[t] - mean; ss += d * d; }
    red[tid] = ss; __syncthreads();
    for (int o = 128; o; o >>= 1) { if (tid < o) red[tid] += red[tid + o]; __syncthreads(); }
    float inv = 1.0f / (sqrtf(red[0] / (float)(T_FRAMES - 1)) + 1e-8f);
    __syncthreads();
    for (int t = tid; t < T_FRAMES; t += 256) cn[t] = (cn[t] - mean) * inv;
    __syncthreads();

    for (int t = tid; t < T_FRAMES; t += 256) {
        int tp1 = min(t + 1, T_FRAMES - 1), tm1 = max(t - 1, 0);
        int tp2 = min(t + 2, T_FRAMES - 1), tm2 = max(t - 2, 0);
        float d = ((cn[tp1] - cn[tm1]) + 2.0f * (cn[tp2] - cn[tm2])) * 0.1f;
        d1s[t] = d;
        out[t * 60 + c]      = cn[t];
        out[t * 60 + 20 + c] = d;
    }
    __syncthreads();
    for (int t = tid; t < T_FRAMES; t += 256) {
        int tp1 = min(t + 1, T_FRAMES - 1), tm1 = max(t - 1, 0);
        int tp2 = min(t + 2, T_FRAMES - 1), tm2 = max(t - 2, 0);
        float d = ((d1s[tp1] - d1s[tm1]) + 2.0f * (d1s[tp2] - d1s[tm2])) * 0.1f;
        out[t * 60 + 40 + c] = d;
    }
}

// ---------------- launch ----------------
extern "C" void kernel_launch(void* const* d_in, const int* in_sizes, int n_in,
                              void* d_out, int out_size) {
    const float* wav = (const float*)d_in[0];
    float* out = (float*)d_out;

    const int s1_smem = (16384 + 128 * 64) * 4;   // 98304
    const int s2_smem = (FTILE2 * GS_STR + FTILE2 * GP_STR + WROWS * FTILE2) * 8;  // ~71.9 KB
    cudaFuncSetAttribute(k_s1, cudaFuncAttributeMaxDynamicSharedMemorySize, s1_smem);
    cudaFuncSetAttribute(k_s2, cudaFuncAttributeMaxDynamicSharedMemorySize, s2_smem);

    k_setup<<<SETUP_BLKS, 256>>>(wav);
    k_s1<<<dim3(36, 18), 256, s1_smem>>>();
    k_s2<<<dim3(FB2, TT2), 256, s2_smem>>>();
    k_ceps<<<257, 256>>>();
    k_tail<<<NC, 256>>>(out);
}

// round 9
// speedup vs baseline: 15.3674x; 1.0817x over previous
#include <cuda_runtime.h>
#include <cstdint>

// ---------------- constants ----------------
#define T_FRAMES 2049
#define NWAV     262144
#define MW       16699
#define LEFT     24418
#define PADR     32768
#define NB       96
#define NC       20
#define NF       576            // 192 bins x 3 sub-frequencies
#define ECOLS    2304           // [full 1152 | partial 1152]
#define GROWS    2368
#define XW_LEN   294912         // 2304*128
#define TPAD     2176

// stage-2 tiling: 18 complex freqs (=3 cqt bins worth of lo/hi) x 112 frames
#define FTILE2   18
#define TTILE2   112
#define TT2      19             // 19*112 = 2128 >= 2049
#define FB2      32             // 576/18
#define GS_STR   247            // float2 stride, rows 0..244
#define HS_STR   233            // float2 stride, rows 0..231
#define GP_STR   113            // rows 0..111
#define ZS_STR   113
#define W2ROWS   24             // 13 H-taps + 10 Z-taps + 1 partial

// setup kernel block ranges
#define PAD_BLKS 1152           // 294912/256
#define E_BLKS   288
#define W_ELEMS  (NF * W2ROWS)  // 13824
#define W_BLKS   54
#define SETUP_BLKS (PAD_BLKS + E_BLKS + W_BLKS + 1)

// ---------------- device scratch ----------------
__device__ float g_xw[XW_LEN];
__device__ float g_e[128 * ECOLS];
__device__ float g_w2[W2ROWS * 1152];
__device__ float g_g[(size_t)GROWS * ECOLS];
__device__ float g_lpT[(size_t)NB * TPAD];      // log cqt power, [bin][t]
__device__ float g_c[T_FRAMES * NC];
__device__ float g_alpha[NB];
__device__ float g_dct[NC * NB];

// ---------------- f32x2 helpers ----------------
__device__ __forceinline__ void fma2(unsigned long long& acc,
                                     unsigned long long a, unsigned long long b) {
    asm("fma.rn.f32x2 %0, %1, %2, %0;" : "+l"(acc) : "l"(a), "l"(b));
}
__device__ __forceinline__ unsigned long long dup2(float x) {
    unsigned long long r;
    asm("mov.b64 %0, {%1, %1};" : "=l"(r) : "f"(x));
    return r;
}
__device__ __forceinline__ unsigned long long pk2(float x, float y) {
    unsigned long long r;
    asm("mov.b64 %0, {%1, %2};" : "=l"(r) : "f"(x), "f"(y));
    return r;
}
__device__ __forceinline__ float2 upk2(unsigned long long v) {
    float2 r;
    asm("mov.b64 {%0, %1}, %2;" : "=f"(r.x), "=f"(r.y) : "l"(v));
    return r;
}

// ---------------- inline bin computation ----------------
__device__ __forceinline__ int bin_of(int bi) {   // bi 0..191
    int i = bi >> 1;
    float cq   = 32.7f * exp2f((float)i / 24.0f);
    float idxf = cq / 8000.0f * 32768.0f;
    int lo = (int)idxf;
    lo = max(0, min(lo, 32767));
    return lo + (bi & 1);
}

// ---------------- fused setup ----------------
__global__ void __launch_bounds__(256) k_setup(const float* __restrict__ wav) {
    const int blk = blockIdx.x;
    const int tid = threadIdx.x;

    if (blk < PAD_BLKS) {
        int i = blk * 256 + tid;
        int q = i + (LEFT - PADR);
        int idx = (q < 0) ? -q : ((q >= NWAV) ? (2 * NWAV - 2 - q) : q);
        idx = max(0, min(idx, NWAV - 1));
        g_xw[i] = wav[idx];
        return;
    }
    if (blk < PAD_BLKS + E_BLKS) {
        int fi = (blk - PAD_BLKS) * 2 + (tid >> 7);
        int r  = tid & 127;
        int bi = fi / 3, j = fi % 3;
        int b  = bin_of(bi);
        float fb = (float)((b * r) & 65535) * (1.0f / 65536.0f);
        float fs = (float)r * (1.0f / (float)MW);
        float fr = fb + ((j == 1) ? -fs : (j == 2) ? fs : 0.0f);
        float s, c;
        sincospif(2.0f * fr, &s, &c);
        float re = c, im = -s;
        g_e[r * ECOLS + 2 * fi]     = re;
        g_e[r * ECOLS + 2 * fi + 1] = im;
        float rp = (r < 59) ? re : 0.0f;
        float ip = (r < 59) ? im : 0.0f;
        g_e[r * ECOLS + 1152 + 2 * fi]     = rp;
        g_e[r * ECOLS + 1152 + 2 * fi + 1] = ip;
        return;
    }
    if (blk < PAD_BLKS + E_BLKS + W_BLKS) {
        int lin = (blk - PAD_BLKS - E_BLKS) * 256 + tid;
        if (lin >= W_ELEMS) return;
        int fi = lin / W2ROWS;
        int u  = lin % W2ROWS;
        int bi = fi / 3, j = fi % 3;
        int b  = bin_of(bi);
        int sgn = (j == 1) ? -1 : (j == 2) ? 1 : 0;
        float wre, wim;
        if (u < 13) {
            // H tap: rho^u, no coeff
            float fa = (float)((b * u) & 511) * (1.0f / 512.0f);
            float fbv = (float)(128 * u) * (1.0f / (float)MW);
            float fr = fa + (float)sgn * fbv;
            float s, c;
            sincospif(2.0f * fr, &s, &c);
            wre = c; wim = -s;
        } else {
            // Z tap: coeff*rho^(13v) for u=13..22, partial tap (exp 130) at u=23
            float coeff = (j == 0) ? 0.5f : -0.25f;
            int e = (u < 23) ? 13 * (u - 13) : 130;
            float fa = (float)((b * e) & 511) * (1.0f / 512.0f);
            float fbv = (float)((128 * e) % MW) * (1.0f / (float)MW);
            float fr = fa + (float)sgn * fbv;
            float s, c;
            sincospif(2.0f * fr, &s, &c);
            wre = coeff * c;
            wim = -coeff * s;
        }
        g_w2[u * 1152 + 2 * fi]     = wre;
        g_w2[u * 1152 + 2 * fi + 1] = wim;
        return;
    }
    // last block: alpha + dct
    if (tid < NB) {
        float cq   = 32.7f * exp2f((float)tid / 24.0f);
        float idxf = cq / 8000.0f * 32768.0f;
        int lo = (int)idxf;
        lo = max(0, min(lo, 32767));
        g_alpha[tid] = idxf - (float)lo;
    }
    for (int idx = tid; idx < NC * NB; idx += 256) {
        int c = idx / NB, n = idx % NB;
        g_dct[idx] = cospif((float)(c * (2 * n + 1)) / 192.0f);
    }
}

// ---------------- stage 1: G[s, col] = sum_r xw[128s + r] * E[r, col] ----------------
__global__ void __launch_bounds__(256) k_s1() {
    extern __shared__ float smem[];
    float* xs = smem;            // 16384 floats
    float* ts = smem + 16384;    // up to 128 x 64

    const int bx = blockIdx.x;                 // 0..35
    const int c0 = bx * 64;
    const int K  = (bx < 18) ? 128 : 64;
    const int s0 = blockIdx.y * 128;
    const int tid = threadIdx.x;
    const int cg = tid & 15;
    const int fg = tid >> 4;

    const float4* xsrc = (const float4*)(g_xw + s0 * 128);
    #pragma unroll
    for (int i = tid; i < 4096; i += 256)
        ((float4*)xs)[i] = xsrc[i];
    for (int i = tid; i < K * 16; i += 256) {
        int kk = i >> 4, c4 = i & 15;
        ((float4*)ts)[i] = *(const float4*)(g_e + kk * ECOLS + c0 + c4 * 4);
    }
    __syncthreads();

    unsigned long long acc[8][2] = {};
    for (int kk0 = 0; kk0 < K; kk0 += 4) {
        float4 af[8];
        #pragma unroll
        for (int r = 0; r < 8; r++)
            af[r] = *(const float4*)(xs + (fg * 8 + r) * 128 + kk0);
        #pragma unroll
        for (int k = 0; k < 4; k++) {
            ulonglong2 bb = *(const ulonglong2*)(ts + (kk0 + k) * 64 + cg * 4);
            #pragma unroll
            for (int r = 0; r < 8; r++) {
                unsigned long long ad = dup2(((const float*)&af[r])[k]);
                fma2(acc[r][0], ad, bb.x);
                fma2(acc[r][1], ad, bb.y);
            }
        }
    }

    #pragma unroll
    for (int r = 0; r < 8; r++) {
        int s = s0 + fg * 8 + r;
        ulonglong2 v;
        v.x = acc[r][0]; v.y = acc[r][1];
        *(ulonglong2*)(g_g + (size_t)s * ECOLS + c0 + cg * 4) = v;
    }
}

// ---------------- stage 2: two-level FIR (13 x 10) + partial + fused power/log ----------------
__global__ void __launch_bounds__(256) k_s2() {
    extern __shared__ float smem[];
    float2* Gs = (float2*)smem;               // [18][GS_STR], rows 0..244
    float2* Hs = Gs + FTILE2 * GS_STR;        // [18][HS_STR], rows 0..231
    float2* Gp = Hs + FTILE2 * HS_STR;        // [18][GP_STR], rows 0..111
    float2* Wt = Gp + FTILE2 * GP_STR;        // [24][18]

    const int m   = blockIdx.x;               // bin-triple 0..31
    const int fc0 = m * FTILE2;
    const int t0  = blockIdx.y * TTILE2;
    const int tid = threadIdx.x;

    for (int idx = tid; idx < 245 * 9; idx += 256) {
        int row = idx / 9, p = idx % 9;
        float4 v = *(const float4*)(g_g + (size_t)(t0 + row) * ECOLS + fc0 * 2 + p * 4);
        Gs[(2 * p) * GS_STR + row]     = make_float2(v.x, v.y);
        Gs[(2 * p + 1) * GS_STR + row] = make_float2(v.z, v.w);
    }
    for (int idx = tid; idx < 112 * 9; idx += 256) {
        int row = idx / 9, p = idx % 9;
        float4 v = *(const float4*)(g_g + (size_t)(t0 + 130 + row) * ECOLS + 1152 + fc0 * 2 + p * 4);
        Gp[(2 * p) * GP_STR + row]     = make_float2(v.x, v.y);
        Gp[(2 * p + 1) * GP_STR + row] = make_float2(v.z, v.w);
    }
    for (int idx = tid; idx < W2ROWS * 9; idx += 256) {
        int u = idx / 9, p = idx % 9;
        float4 v = *(const float4*)(g_w2 + u * 1152 + fc0 * 2 + p * 4);
        Wt[u * FTILE2 + 2 * p]     = make_float2(v.x, v.y);
        Wt[u * FTILE2 + 2 * p + 1] = make_float2(v.z, v.w);
    }
    __syncthreads();

    // ---- H phase: H[tau,f] = sum_{w<13} rho^w G[tau+w,f], rows 0..231 ----
    for (int cid = tid; cid < 522; cid += 256) {     // 18 f x 29 chunks of 8 rows
        int f = cid % 18, ch = cid / 18;
        int base = ch * 8;
        const float2* gb = Gs + f * GS_STR + base;
        unsigned long long gw[8], gsw[8], acc[8];
        #pragma unroll
        for (int r = 0; r < 8; r++) acc[r] = 0ULL;
        #pragma unroll
        for (int i = 0; i < 7; i++) {
            float2 g = gb[i];
            gw[i]  = pk2(g.x, g.y);
            gsw[i] = pk2(-g.y, g.x);
        }
        #pragma unroll
        for (int u = 0; u < 13; u++) {
            float2 g = gb[u + 7];
            gw[(u + 7) & 7]  = pk2(g.x, g.y);
            gsw[(u + 7) & 7] = pk2(-g.y, g.x);
            float2 wt = Wt[u * FTILE2 + f];
            unsigned long long wx = dup2(wt.x);
            unsigned long long wy = dup2(wt.y);
            #pragma unroll
            for (int r = 0; r < 8; r++) {
                fma2(acc[r], wx, gw[(u + r) & 7]);
                fma2(acc[r], wy, gsw[(u + r) & 7]);
            }
        }
        float2* hb = Hs + f * HS_STR + base;
        #pragma unroll
        for (int r = 0; r < 8; r++) hb[r] = upk2(acc[r]);
    }
    __syncthreads();

    // ---- Z phase: Z[t,f] = sum_{v<10} (coeff*rho^13v) H[t+13v,f] + partial ----
    const int f  = tid % 18;
    const int tg = tid / 18;
    const bool active = (tid < 252);
    const int base = tg * 8;
    unsigned long long acc[8] = {};
    if (active) {
        const float2* hb = Hs + f * HS_STR + base;
        #pragma unroll
        for (int v = 0; v < 10; v++) {
            float2 wt = Wt[(13 + v) * FTILE2 + f];
            unsigned long long wx = dup2(wt.x);
            unsigned long long wy = dup2(wt.y);
            #pragma unroll
            for (int r = 0; r < 8; r++) {
                float2 h = hb[13 * v + r];
                fma2(acc[r], wx, pk2(h.x, h.y));
                fma2(acc[r], wy, pk2(-h.y, h.x));
            }
        }
        float2 wt = Wt[23 * FTILE2 + f];
        unsigned long long wx = dup2(wt.x);
        unsigned long long wy = dup2(wt.y);
        const float2* gp = Gp + f * GP_STR + base;
        #pragma unroll
        for (int r = 0; r < 8; r++) {
            float2 g = gp[r];
            fma2(acc[r], wx, pk2(g.x, g.y));
            fma2(acc[r], wy, pk2(-g.y, g.x));
        }
    }
    __syncthreads();                           // Gs fully consumed; reuse as Zs
    float2* Zs = Gs;
    if (active) {
        #pragma unroll
        for (int r = 0; r < 8; r++)
            Zs[f * ZS_STR + base + r] = upk2(acc[r]);
    }
    __syncthreads();

    // ---- combine triples -> power -> lerp -> log ----
    for (int idx = tid; idx < 3 * TTILE2; idx += 256) {
        int q  = idx / TTILE2;
        int tl = idx % TTILE2;
        int t  = t0 + tl;
        if (t >= T_FRAMES) continue;
        const float2* zq = Zs + (6 * q) * ZS_STR + tl;
        float2 z0 = zq[0];
        float2 z1 = zq[ZS_STR];
        float2 z2 = zq[2 * ZS_STR];
        float2 z3 = zq[3 * ZS_STR];
        float2 z4 = zq[4 * ZS_STR];
        float2 z5 = zq[5 * ZS_STR];
        float lre = z0.x + z1.x + z2.x, lim = z0.y + z1.y + z2.y;
        float hre = z3.x + z4.x + z5.x, him = z3.y + z4.y + z5.y;
        float plo = lre * lre + lim * lim;
        float phi = hre * hre + him * him;
        int bin = 3 * m + q;
        float al = g_alpha[bin];
        float p = (1.0f - al) * plo + al * phi;
        g_lpT[(size_t)bin * TPAD + t] = logf(fmaxf(p, 1e-8f));
    }
}

// ---------------- ceps: tiled DCT over g_lpT ----------------
__global__ void __launch_bounds__(256) k_ceps() {
    extern __shared__ float smem[];
    float* lps  = smem;               // [96][132]
    float* dctt = smem + 96 * 132;    // [20][96]
    const int tid = threadIdx.x;
    const int t0 = blockIdx.x * 128;

    for (int idx = tid; idx < 96 * 32; idx += 256) {
        int n = idx >> 5, p = idx & 31;
        float4 v = *(const float4*)(g_lpT + (size_t)n * TPAD + t0 + p * 4);
        *(float4*)(lps + n * 132 + p * 4) = v;
    }
    for (int idx = tid; idx < NC * NB; idx += 256) dctt[idx] = g_dct[idx];
    __syncthreads();

    const int w = tid >> 5, lane = tid & 31;
    const int c0 = (w & 3) * 5;
    const int tb = (w >> 2) * 64 + lane * 2;

    unsigned long long acc[5] = {};
    #pragma unroll 4
    for (int n = 0; n < NB; n++) {
        unsigned long long gv = *(const unsigned long long*)(lps + n * 132 + tb);
        #pragma unroll
        for (int k = 0; k < 5; k++)
            fma2(acc[k], dup2(dctt[(c0 + k) * NB + n]), gv);
    }
    int t = t0 + tb;
    #pragma unroll
    for (int k = 0; k < 5; k++) {
        float2 r = upk2(acc[k]);
        if (t < T_FRAMES)     g_c[t * NC + c0 + k] = r.x;
        if (t + 1 < T_FRAMES) g_c[(t + 1) * NC + c0 + k] = r.y;
    }
}

// ---------------- fused normalize + delta + delta-delta ----------------
__global__ void __launch_bounds__(256) k_tail(float* __restrict__ out) {
    const int c = blockIdx.x;       // 0..19
    const int tid = threadIdx.x;
    __shared__ float cn[T_FRAMES];
    __shared__ float d1s[T_FRAMES];
    __shared__ float red[256];

    float s = 0.0f;
    for (int t = tid; t < T_FRAMES; t += 256) {
        float v = g_c[t * NC + c];
        cn[t] = v;
        s += v;
    }
    red[tid] = s; __syncthreads();
    for (int o = 128; o; o >>= 1) { if (tid < o) red[tid] += red[tid + o]; __syncthreads(); }
    float mean = red[0] / (float)T_FRAMES;
    __syncthreads();
    float ss = 0.0f;
    for (int t = tid; t < T_FRAMES; t += 256) { float d = cn[t] - mean; ss += d * d; }
    red[tid] = ss; __syncthreads();
    for (int o = 128; o; o >>= 1) { if (tid < o) red[tid] += red[tid + o]; __syncthreads(); }
    float inv = 1.0f / (sqrtf(red[0] / (float)(T_FRAMES - 1)) + 1e-8f);
    __syncthreads();
    for (int t = tid; t < T_FRAMES; t += 256) cn[t] = (cn[t] - mean) * inv;
    __syncthreads();

    for (int t = tid; t < T_FRAMES; t += 256) {
        int tp1 = min(t + 1, T_FRAMES - 1), tm1 = max(t - 1, 0);
        int tp2 = min(t + 2, T_FRAMES - 1), tm2 = max(t - 2, 0);
        float d = ((cn[tp1] - cn[tm1]) + 2.0f * (cn[tp2] - cn[tm2])) * 0.1f;
        d1s[t] = d;
        out[t * 60 + c]      = cn[t];
        out[t * 60 + 20 + c] = d;
    }
    __syncthreads();
    for (int t = tid; t < T_FRAMES; t += 256) {
        int tp1 = min(t + 1, T_FRAMES - 1), tm1 = max(t - 1, 0);
        int tp2 = min(t + 2, T_FRAMES - 1), tm2 = max(t - 2, 0);
        float d = ((d1s[tp1] - d1s[tm1]) + 2.0f * (d1s[tp2] - d1s[tm2])) * 0.1f;
        out[t * 60 + 40 + c] = d;
    }
}

// ---------------- launch ----------------
extern "C" void kernel_launch(void* const* d_in, const int* in_sizes, int n_in,
                              void* d_out, int out_size) {
    const float* wav = (const float*)d_in[0];
    float* out = (float*)d_out;

    const int s1_smem = (16384 + 128 * 64) * 4;   // 98304
    const int s2_smem = (FTILE2 * GS_STR + FTILE2 * HS_STR + FTILE2 * GP_STR
                         + W2ROWS * FTILE2) * 8;  // 88848
    const int ceps_smem = (96 * 132 + NC * NB) * 4;  // 58368
    cudaFuncSetAttribute(k_s1, cudaFuncAttributeMaxDynamicSharedMemorySize, s1_smem);
    cudaFuncSetAttribute(k_s2, cudaFuncAttributeMaxDynamicSharedMemorySize, s2_smem);
    cudaFuncSetAttribute(k_ceps, cudaFuncAttributeMaxDynamicSharedMemorySize, ceps_smem);

    k_setup<<<SETUP_BLKS, 256>>>(wav);
    k_s1<<<dim3(36, 18), 256, s1_smem>>>();
    k_s2<<<dim3(FB2, TT2), 256, s2_smem>>>();
    k_ceps<<<17, 256, ceps_smem>>>();
    k_tail<<<NC, 256>>>(out);
}